// round 1
// baseline (speedup 1.0000x reference)
#include <cuda_runtime.h>
#include <cuda_bf16.h>
#include <math.h>

// Problem constants
#define Bc 4
#define Sc 2048
#define Dc 1024
#define Hc 16
#define DKc 64
#define MROWS (Bc * Sc)   // 8192

// Scratch: Q, K, V projections and attention output (each 8192x1024 fp32 = 32MB)
__device__ float g_Q[MROWS * Dc];
__device__ float g_K[MROWS * Dc];
__device__ float g_V[MROWS * Dc];
__device__ float g_A[MROWS * Dc];

// ---------------------------------------------------------------------------
// SGEMM: C[M,N] = A[M,K] * W[K,N] + bias[N]
// BM=BN=128, BK=16, 256 threads (16x16), 8x8 register tile per thread.
// ---------------------------------------------------------------------------
__global__ void __launch_bounds__(256) gemm_bias_kernel(
    const float* __restrict__ A, const float* __restrict__ W,
    const float* __restrict__ bias, float* __restrict__ C,
    int M, int N, int K)
{
    __shared__ float As[16][128];   // [k][m] (transposed)
    __shared__ float Bs[16][128];   // [k][n]

    const int tid = threadIdx.x;
    const int tx  = tid & 15;
    const int ty  = tid >> 4;
    const int m0  = blockIdx.y * 128;
    const int n0  = blockIdx.x * 128;

    float acc[8][8];
#pragma unroll
    for (int i = 0; i < 8; i++)
#pragma unroll
        for (int j = 0; j < 8; j++) acc[i][j] = 0.f;

    for (int k0 = 0; k0 < K; k0 += 16) {
        __syncthreads();
#pragma unroll
        for (int it = 0; it < 2; ++it) {
            int idx = tid + it * 256;
            // A tile: 128 rows x 16 cols = 512 float4
            int mm = idx >> 2;
            int k4 = (idx & 3) * 4;
            float4 av = *(const float4*)(A + (size_t)(m0 + mm) * K + k0 + k4);
            As[k4 + 0][mm] = av.x;
            As[k4 + 1][mm] = av.y;
            As[k4 + 2][mm] = av.z;
            As[k4 + 3][mm] = av.w;
            // B tile: 16 rows x 128 cols = 512 float4
            int kr = idx >> 5;
            int n4 = (idx & 31) * 4;
            float4 bv = *(const float4*)(W + (size_t)(k0 + kr) * N + n0 + n4);
            *(float4*)&Bs[kr][n4] = bv;
        }
        __syncthreads();

#pragma unroll
        for (int kk = 0; kk < 16; ++kk) {
            float a[8], b[8];
            *(float4*)&a[0] = *(const float4*)&As[kk][ty * 8];
            *(float4*)&a[4] = *(const float4*)&As[kk][ty * 8 + 4];
            *(float4*)&b[0] = *(const float4*)&Bs[kk][tx * 8];
            *(float4*)&b[4] = *(const float4*)&Bs[kk][tx * 8 + 4];
#pragma unroll
            for (int i = 0; i < 8; i++)
#pragma unroll
                for (int j = 0; j < 8; j++)
                    acc[i][j] = fmaf(a[i], b[j], acc[i][j]);
        }
    }

    // Epilogue: add bias, write out (vectorized)
#pragma unroll
    for (int i = 0; i < 8; i++) {
        size_t row = (size_t)(m0 + ty * 8 + i);
#pragma unroll
        for (int j4 = 0; j4 < 2; j4++) {
            int col = n0 + tx * 8 + j4 * 4;
            float4 bv = *(const float4*)(bias + col);
            float4 cv;
            cv.x = acc[i][j4 * 4 + 0] + bv.x;
            cv.y = acc[i][j4 * 4 + 1] + bv.y;
            cv.z = acc[i][j4 * 4 + 2] + bv.z;
            cv.w = acc[i][j4 * 4 + 3] + bv.w;
            *(float4*)(C + row * N + col) = cv;
        }
    }
}

// ---------------------------------------------------------------------------
// Flash attention (fp32): per (b,h), tiles of BQ=64 queries x BKV=64 keys.
// Online softmax, O accumulated in registers (4x4 per thread, 16x16 threads).
// Dynamic smem: Qs[64][64] ([dk][q]), Ks[64][64] ([dk][k]),
//               Vs[64][64] ([k][dk]), Ps[64][68] ([k][q], padded).
// ---------------------------------------------------------------------------
#define BQ 64
#define BKV 64
#define PS_STRIDE 68
#define ATTN_SMEM_FLOATS (64*64 + 64*64 + 64*64 + 64*PS_STRIDE)

__global__ void __launch_bounds__(256) attn_kernel()
{
    extern __shared__ float sm[];
    float* Qs = sm;                      // [dk*64 + q]
    float* Ks = sm + 64 * 64;            // [dk*64 + k]
    float* Vs = sm + 2 * 64 * 64;        // [k*64 + dk]
    float* Ps = sm + 3 * 64 * 64;        // [k*PS_STRIDE + q]

    const int qt  = blockIdx.x;          // query tile, 0..31
    const int bh  = blockIdx.y;          // 0..63
    const int b   = bh >> 4;
    const int h   = bh & 15;
    const int tid = threadIdx.x;
    const int tx  = tid & 15;
    const int ty  = tid >> 4;
    const int q0  = qt * BQ;

    const float* Qg = g_Q + (size_t)b * Sc * Dc + (size_t)h * DKc;
    const float* Kg = g_K + (size_t)b * Sc * Dc + (size_t)h * DKc;
    const float* Vg = g_V + (size_t)b * Sc * Dc + (size_t)h * DKc;

    // Load Q tile transposed ([dk][q]) with 1/sqrt(DK) pre-applied
#pragma unroll
    for (int it = 0; it < 4; ++it) {
        int idx = tid + it * 256;        // 0..1023
        int qi  = idx >> 4;
        int d4  = (idx & 15) * 4;
        float4 v = *(const float4*)(Qg + (size_t)(q0 + qi) * Dc + d4);
        Qs[(d4 + 0) * 64 + qi] = v.x * 0.125f;
        Qs[(d4 + 1) * 64 + qi] = v.y * 0.125f;
        Qs[(d4 + 2) * 64 + qi] = v.z * 0.125f;
        Qs[(d4 + 3) * 64 + qi] = v.w * 0.125f;
    }

    float mrow[4], lrow[4], o[4][4];
#pragma unroll
    for (int i = 0; i < 4; i++) {
        mrow[i] = -INFINITY;
        lrow[i] = 0.f;
#pragma unroll
        for (int j = 0; j < 4; j++) o[i][j] = 0.f;
    }

    for (int kt = 0; kt < Sc / BKV; ++kt) {
        __syncthreads();  // prev PV done (and Q load visible on 1st iter)
        const int k0 = kt * BKV;
        // Load K tile transposed ([dk][k]) + V tile direct ([k][dk])
#pragma unroll
        for (int it = 0; it < 4; ++it) {
            int idx = tid + it * 256;
            int ki  = idx >> 4;
            int d4  = (idx & 15) * 4;
            float4 kv = *(const float4*)(Kg + (size_t)(k0 + ki) * Dc + d4);
            Ks[(d4 + 0) * 64 + ki] = kv.x;
            Ks[(d4 + 1) * 64 + ki] = kv.y;
            Ks[(d4 + 2) * 64 + ki] = kv.z;
            Ks[(d4 + 3) * 64 + ki] = kv.w;
            float4 vv = *(const float4*)(Vg + (size_t)(k0 + ki) * Dc + d4);
            *(float4*)&Vs[ki * 64 + d4] = vv;
        }
        __syncthreads();

        // Scores tile: s[i][j] = (q_scaled . k), 4x4 per thread
        float s[4][4];
#pragma unroll
        for (int i = 0; i < 4; i++)
#pragma unroll
            for (int j = 0; j < 4; j++) s[i][j] = 0.f;

#pragma unroll 16
        for (int dk = 0; dk < DKc; ++dk) {
            float4 qa = *(const float4*)&Qs[dk * 64 + ty * 4];
            float4 kb = *(const float4*)&Ks[dk * 64 + tx * 4];
            float aq[4] = {qa.x, qa.y, qa.z, qa.w};
            float bk[4] = {kb.x, kb.y, kb.z, kb.w};
#pragma unroll
            for (int i = 0; i < 4; i++)
#pragma unroll
                for (int j = 0; j < 4; j++)
                    s[i][j] = fmaf(aq[i], bk[j], s[i][j]);
        }

        // Online softmax per query row (reduction across 16 tx threads = half warp)
#pragma unroll
        for (int i = 0; i < 4; i++) {
            float mx = fmaxf(fmaxf(s[i][0], s[i][1]), fmaxf(s[i][2], s[i][3]));
            mx = fmaxf(mx, __shfl_xor_sync(0xffffffffu, mx, 1));
            mx = fmaxf(mx, __shfl_xor_sync(0xffffffffu, mx, 2));
            mx = fmaxf(mx, __shfl_xor_sync(0xffffffffu, mx, 4));
            mx = fmaxf(mx, __shfl_xor_sync(0xffffffffu, mx, 8));
            float mn   = fmaxf(mrow[i], mx);
            float corr = __expf(mrow[i] - mn);
            mrow[i] = mn;
            float sum = 0.f;
#pragma unroll
            for (int j = 0; j < 4; j++) {
                float p = __expf(s[i][j] - mn);
                s[i][j] = p;
                sum += p;
            }
            sum += __shfl_xor_sync(0xffffffffu, sum, 1);
            sum += __shfl_xor_sync(0xffffffffu, sum, 2);
            sum += __shfl_xor_sync(0xffffffffu, sum, 4);
            sum += __shfl_xor_sync(0xffffffffu, sum, 8);
            lrow[i] = lrow[i] * corr + sum;
#pragma unroll
            for (int j = 0; j < 4; j++) o[i][j] *= corr;
        }

        // Write P transposed: Ps[kcol][qrow]
#pragma unroll
        for (int j = 0; j < 4; j++)
#pragma unroll
            for (int i = 0; i < 4; i++)
                Ps[(tx * 4 + j) * PS_STRIDE + ty * 4 + i] = s[i][j];
        __syncthreads();

        // O += P @ V
#pragma unroll 16
        for (int k = 0; k < BKV; ++k) {
            float4 pa = *(const float4*)&Ps[k * PS_STRIDE + ty * 4];
            float4 vb = *(const float4*)&Vs[k * 64 + tx * 4];
            float pp[4] = {pa.x, pa.y, pa.z, pa.w};
            float vv[4] = {vb.x, vb.y, vb.z, vb.w};
#pragma unroll
            for (int i = 0; i < 4; i++)
#pragma unroll
                for (int j = 0; j < 4; j++)
                    o[i][j] = fmaf(pp[i], vv[j], o[i][j]);
        }
    }

    // Epilogue: normalize and store to g_A[b*S + q][h*DK + dk]
    float* Og = g_A + (size_t)b * Sc * Dc + (size_t)h * DKc;
#pragma unroll
    for (int i = 0; i < 4; i++) {
        float inv = 1.f / lrow[i];
        size_t row = (size_t)(q0 + ty * 4 + i);
        float4 cv;
        cv.x = o[i][0] * inv;
        cv.y = o[i][1] * inv;
        cv.z = o[i][2] * inv;
        cv.w = o[i][3] * inv;
        *(float4*)(Og + row * Dc + tx * 4) = cv;
    }
}

// ---------------------------------------------------------------------------
// Launch
// ---------------------------------------------------------------------------
extern "C" void kernel_launch(void* const* d_in, const int* in_sizes, int n_in,
                              void* d_out, int out_size)
{
    const float* q  = (const float*)d_in[0];
    const float* k  = (const float*)d_in[1];
    const float* v  = (const float*)d_in[2];
    const float* wq = (const float*)d_in[3];
    const float* bq = (const float*)d_in[4];
    const float* wk = (const float*)d_in[5];
    const float* bk = (const float*)d_in[6];
    const float* wv = (const float*)d_in[7];
    const float* bv = (const float*)d_in[8];
    const float* wo = (const float*)d_in[9];
    const float* bo = (const float*)d_in[10];
    float* out = (float*)d_out;

    float *pQ, *pK, *pV, *pA;
    cudaGetSymbolAddress((void**)&pQ, g_Q);
    cudaGetSymbolAddress((void**)&pK, g_K);
    cudaGetSymbolAddress((void**)&pV, g_V);
    cudaGetSymbolAddress((void**)&pA, g_A);

    const int smem_bytes = ATTN_SMEM_FLOATS * sizeof(float);
    cudaFuncSetAttribute(attn_kernel, cudaFuncAttributeMaxDynamicSharedMemorySize,
                         smem_bytes);

    dim3 gblk(256);
    dim3 ggrid(Dc / 128, MROWS / 128);   // (8, 64)

    // Projections
    gemm_bias_kernel<<<ggrid, gblk>>>(q, wq, bq, pQ, MROWS, Dc, Dc);
    gemm_bias_kernel<<<ggrid, gblk>>>(k, wk, bk, pK, MROWS, Dc, Dc);
    gemm_bias_kernel<<<ggrid, gblk>>>(v, wv, bv, pV, MROWS, Dc, Dc);

    // Attention
    dim3 agrid(Sc / BQ, Bc * Hc);        // (32, 64)
    attn_kernel<<<agrid, 256, smem_bytes>>>();

    // Output projection
    gemm_bias_kernel<<<ggrid, gblk>>>(pA, wo, bo, out, MROWS, Dc, Dc);
}

// round 3
// speedup vs baseline: 1.2485x; 1.2485x over previous
#include <cuda_runtime.h>
#include <cuda_bf16.h>
#include <math.h>
#include <stdint.h>

// Problem constants
#define Bc 4
#define Sc 2048
#define Dc 1024
#define Hc 16
#define DKc 64
#define MROWS (Bc * Sc)   // 8192

// fp32 scratch
__device__ float g_Q[MROWS * Dc];
__device__ float g_K[MROWS * Dc];
__device__ float g_V[MROWS * Dc];
__device__ float g_A[MROWS * Dc];
// bf16 split scratch (reused across GEMMs; stream-ordered)
__device__ __nv_bfloat16 g_Xh[MROWS * Dc];
__device__ __nv_bfloat16 g_Xl[MROWS * Dc];
__device__ __nv_bfloat16 g_Wh[Dc * Dc];   // transposed weight [N][K], hi
__device__ __nv_bfloat16 g_Wl[Dc * Dc];   // transposed weight [N][K], lo

// ---------------------------------------------------------------------------
// Warp-MMA helpers (sm_80-class PTX; legal on plain sm_103 target)
// ---------------------------------------------------------------------------
__device__ __forceinline__ uint32_t smem_u32(const void* p) {
    uint32_t a;
    asm("{ .reg .u64 t; cvta.to.shared.u64 t, %1; cvt.u32.u64 %0, t; }"
        : "=r"(a) : "l"(p));
    return a;
}

__device__ __forceinline__ void ldsm_x4(uint32_t& r0, uint32_t& r1,
                                        uint32_t& r2, uint32_t& r3,
                                        uint32_t addr) {
    asm volatile("ldmatrix.sync.aligned.m8n8.x4.shared.b16 {%0,%1,%2,%3}, [%4];"
                 : "=r"(r0), "=r"(r1), "=r"(r2), "=r"(r3) : "r"(addr));
}

__device__ __forceinline__ void mma_bf16(float* c, const uint32_t* a,
                                         uint32_t b0, uint32_t b1) {
    asm volatile(
        "mma.sync.aligned.m16n8k16.row.col.f32.bf16.bf16.f32 "
        "{%0,%1,%2,%3}, {%4,%5,%6,%7}, {%8,%9}, {%0,%1,%2,%3};"
        : "+f"(c[0]), "+f"(c[1]), "+f"(c[2]), "+f"(c[3])
        : "r"(a[0]), "r"(a[1]), "r"(a[2]), "r"(a[3]), "r"(b0), "r"(b1));
}

// ---------------------------------------------------------------------------
// fp32 -> (bf16 hi, bf16 lo) elementwise split (activations)
// ---------------------------------------------------------------------------
__global__ void __launch_bounds__(256) conv_act_kernel(
    const float* __restrict__ X,
    __nv_bfloat16* __restrict__ H, __nv_bfloat16* __restrict__ L, int n4)
{
    int i = blockIdx.x * blockDim.x + threadIdx.x;
    if (i >= n4) return;
    float4 v = ((const float4*)X)[i];
    float f[4] = {v.x, v.y, v.z, v.w};
    uint32_t hp[2], lp[2];
#pragma unroll
    for (int j = 0; j < 2; j++) {
        __nv_bfloat16 h0 = __float2bfloat16(f[2*j]);
        __nv_bfloat16 h1 = __float2bfloat16(f[2*j+1]);
        __nv_bfloat16 l0 = __float2bfloat16(f[2*j]   - __bfloat162float(h0));
        __nv_bfloat16 l1 = __float2bfloat16(f[2*j+1] - __bfloat162float(h1));
        hp[j] = (uint32_t)__bfloat16_as_ushort(h0) | ((uint32_t)__bfloat16_as_ushort(h1) << 16);
        lp[j] = (uint32_t)__bfloat16_as_ushort(l0) | ((uint32_t)__bfloat16_as_ushort(l1) << 16);
    }
    ((uint2*)H)[i] = make_uint2(hp[0], hp[1]);
    ((uint2*)L)[i] = make_uint2(lp[0], lp[1]);
}

// ---------------------------------------------------------------------------
// Weight [K,N] -> transposed split [N,K] hi/lo (tiled smem transpose)
// ---------------------------------------------------------------------------
__global__ void __launch_bounds__(256) conv_wT_kernel(
    const float* __restrict__ W,
    __nv_bfloat16* __restrict__ Th, __nv_bfloat16* __restrict__ Tl)
{
    __shared__ float t[32][33];
    int n0 = blockIdx.x * 32;
    int k0 = blockIdx.y * 32;
    int tx = threadIdx.x, ty = threadIdx.y;   // (32, 8)
#pragma unroll
    for (int i = 0; i < 4; i++)
        t[ty + 8*i][tx] = W[(size_t)(k0 + ty + 8*i) * Dc + n0 + tx];
    __syncthreads();
#pragma unroll
    for (int i = 0; i < 4; i++) {
        float v = t[tx][ty + 8*i];
        __nv_bfloat16 h = __float2bfloat16(v);
        __nv_bfloat16 l = __float2bfloat16(v - __bfloat162float(h));
        size_t idx = (size_t)(n0 + ty + 8*i) * Dc + k0 + tx;
        Th[idx] = h;
        Tl[idx] = l;
    }
}

// ---------------------------------------------------------------------------
// mma.sync bf16 split-3 GEMM: C[M,N] = (Ah+Al)[M,K] @ (Bh+Bl)[N,K]^T + bias
// Tile 128x128, BK=32, 256 threads = 8 warps (4m x 2n), warp tile 32x64.
// Smem tiles 128x32 bf16 (64B rows), XOR-swizzled 16B chunks:
//   off(row, ch) = row*64 + ((ch ^ ((row>>1)&3)) << 4)
// ---------------------------------------------------------------------------
__global__ void __launch_bounds__(256) gemm_tc_kernel(
    const __nv_bfloat16* __restrict__ Ah, const __nv_bfloat16* __restrict__ Al,
    const __nv_bfloat16* __restrict__ Bh, const __nv_bfloat16* __restrict__ Bl,
    const float* __restrict__ bias, float* __restrict__ C)
{
    __shared__ __align__(128) char smem[32768];   // Ah,Al,Bh,Bl tiles @ 8KB each
    const uint32_t sb = smem_u32(smem);

    const int tid    = threadIdx.x;
    const int lane   = tid & 31;
    const int wid    = tid >> 5;
    const int warp_m = wid >> 1;          // 0..3
    const int warp_n = wid & 1;           // 0..1
    const int m0     = blockIdx.y * 128;
    const int n0     = blockIdx.x * 128;

    float acc[2][8][4];
#pragma unroll
    for (int mt = 0; mt < 2; mt++)
#pragma unroll
        for (int nt = 0; nt < 8; nt++)
#pragma unroll
            for (int e = 0; e < 4; e++) acc[mt][nt][e] = 0.f;

    // Precompute per-lane ldmatrix addresses (kt-invariant).
    uint32_t aAddr[2][2], bAddr[4][2];
#pragma unroll
    for (int mt = 0; mt < 2; mt++)
#pragma unroll
        for (int ks = 0; ks < 2; ks++) {
            int row = warp_m * 32 + mt * 16 + (lane & 15);
            int ch  = ks * 2 + (lane >> 4);
            aAddr[mt][ks] = sb + row * 64 + ((ch ^ ((row >> 1) & 3)) << 4);
        }
#pragma unroll
    for (int j = 0; j < 4; j++)
#pragma unroll
        for (int ks = 0; ks < 2; ks++) {
            int row = warp_n * 64 + j * 16 + ((lane >> 4) << 3) + (lane & 7);
            int ch  = ks * 2 + ((lane >> 3) & 1);
            bAddr[j][ks] = sb + 16384 + row * 64 + ((ch ^ ((row >> 1) & 3)) << 4);
        }

    for (int kt = 0; kt < Dc / 32; ++kt) {
        const int k0 = kt * 32;
        __syncthreads();
        // Load 4 tiles of 128x32 bf16 (512 x 16B chunks each).
        const __nv_bfloat16* gsrc[4] = {Ah, Al, Bh, Bl};
        const int rowbase[4] = {m0, m0, n0, n0};
#pragma unroll
        for (int i = 0; i < 8; ++i) {
            const int t  = i >> 1;
            const int c  = tid + (i & 1) * 256;   // 0..511
            const int row = c >> 2;
            const int ch  = c & 3;
            uint32_t so = (uint32_t)(t * 8192 + row * 64 +
                                     ((ch ^ ((row >> 1) & 3)) << 4));
            size_t gi = (((size_t)(rowbase[t] + row)) << 10) + k0 + ch * 8;
            *(uint4*)(smem + so) = *(const uint4*)(gsrc[t] + gi);
        }
        __syncthreads();

#pragma unroll
        for (int ks = 0; ks < 2; ++ks) {
            uint32_t ah[2][4], al[2][4];
#pragma unroll
            for (int mt = 0; mt < 2; mt++) {
                ldsm_x4(ah[mt][0], ah[mt][1], ah[mt][2], ah[mt][3], aAddr[mt][ks]);
                ldsm_x4(al[mt][0], al[mt][1], al[mt][2], al[mt][3], aAddr[mt][ks] + 8192);
            }
#pragma unroll
            for (int j = 0; j < 4; ++j) {
                uint32_t b4[4];
                ldsm_x4(b4[0], b4[1], b4[2], b4[3], bAddr[j][ks]);     // Bh
#pragma unroll
                for (int mt = 0; mt < 2; mt++) {
                    mma_bf16(acc[mt][2*j],   ah[mt], b4[0], b4[1]);    // Ah.Bh
                    mma_bf16(acc[mt][2*j+1], ah[mt], b4[2], b4[3]);
                    mma_bf16(acc[mt][2*j],   al[mt], b4[0], b4[1]);    // Al.Bh
                    mma_bf16(acc[mt][2*j+1], al[mt], b4[2], b4[3]);
                }
                ldsm_x4(b4[0], b4[1], b4[2], b4[3], bAddr[j][ks] + 8192);  // Bl
#pragma unroll
                for (int mt = 0; mt < 2; mt++) {
                    mma_bf16(acc[mt][2*j],   ah[mt], b4[0], b4[1]);    // Ah.Bl
                    mma_bf16(acc[mt][2*j+1], ah[mt], b4[2], b4[3]);
                }
            }
        }
    }

    // Epilogue: add bias, write fp32.
    const int trow = lane >> 2;
    const int tcol = (lane & 3) * 2;
#pragma unroll
    for (int mt = 0; mt < 2; mt++) {
        const int r0 = m0 + warp_m * 32 + mt * 16 + trow;
#pragma unroll
        for (int nt = 0; nt < 8; nt++) {
            const int col = n0 + warp_n * 64 + nt * 8 + tcol;
            float2 b2 = *(const float2*)(bias + col);
            float2 v0 = {acc[mt][nt][0] + b2.x, acc[mt][nt][1] + b2.y};
            float2 v1 = {acc[mt][nt][2] + b2.x, acc[mt][nt][3] + b2.y};
            *(float2*)(C + (size_t)r0 * Dc + col)       = v0;
            *(float2*)(C + (size_t)(r0 + 8) * Dc + col) = v1;
        }
    }
}

// ---------------------------------------------------------------------------
// Flash attention (fp32) — unchanged
// ---------------------------------------------------------------------------
#define BQ 64
#define BKV 64
#define PS_STRIDE 68
#define ATTN_SMEM_FLOATS (64*64 + 64*64 + 64*64 + 64*PS_STRIDE)

__global__ void __launch_bounds__(256) attn_kernel()
{
    extern __shared__ float sm[];
    float* Qs = sm;
    float* Ks = sm + 64 * 64;
    float* Vs = sm + 2 * 64 * 64;
    float* Ps = sm + 3 * 64 * 64;

    const int qt  = blockIdx.x;
    const int bh  = blockIdx.y;
    const int b   = bh >> 4;
    const int h   = bh & 15;
    const int tid = threadIdx.x;
    const int tx  = tid & 15;
    const int ty  = tid >> 4;
    const int q0  = qt * BQ;

    const float* Qg = g_Q + (size_t)b * Sc * Dc + (size_t)h * DKc;
    const float* Kg = g_K + (size_t)b * Sc * Dc + (size_t)h * DKc;
    const float* Vg = g_V + (size_t)b * Sc * Dc + (size_t)h * DKc;

#pragma unroll
    for (int it = 0; it < 4; ++it) {
        int idx = tid + it * 256;
        int qi  = idx >> 4;
        int d4  = (idx & 15) * 4;
        float4 v = *(const float4*)(Qg + (size_t)(q0 + qi) * Dc + d4);
        Qs[(d4 + 0) * 64 + qi] = v.x * 0.125f;
        Qs[(d4 + 1) * 64 + qi] = v.y * 0.125f;
        Qs[(d4 + 2) * 64 + qi] = v.z * 0.125f;
        Qs[(d4 + 3) * 64 + qi] = v.w * 0.125f;
    }

    float mrow[4], lrow[4], o[4][4];
#pragma unroll
    for (int i = 0; i < 4; i++) {
        mrow[i] = -INFINITY;
        lrow[i] = 0.f;
#pragma unroll
        for (int j = 0; j < 4; j++) o[i][j] = 0.f;
    }

    for (int kt = 0; kt < Sc / BKV; ++kt) {
        __syncthreads();
        const int k0 = kt * BKV;
#pragma unroll
        for (int it = 0; it < 4; ++it) {
            int idx = tid + it * 256;
            int ki  = idx >> 4;
            int d4  = (idx & 15) * 4;
            float4 kv = *(const float4*)(Kg + (size_t)(k0 + ki) * Dc + d4);
            Ks[(d4 + 0) * 64 + ki] = kv.x;
            Ks[(d4 + 1) * 64 + ki] = kv.y;
            Ks[(d4 + 2) * 64 + ki] = kv.z;
            Ks[(d4 + 3) * 64 + ki] = kv.w;
            float4 vv = *(const float4*)(Vg + (size_t)(k0 + ki) * Dc + d4);
            *(float4*)&Vs[ki * 64 + d4] = vv;
        }
        __syncthreads();

        float s[4][4];
#pragma unroll
        for (int i = 0; i < 4; i++)
#pragma unroll
            for (int j = 0; j < 4; j++) s[i][j] = 0.f;

#pragma unroll 16
        for (int dk = 0; dk < DKc; ++dk) {
            float4 qa = *(const float4*)&Qs[dk * 64 + ty * 4];
            float4 kb = *(const float4*)&Ks[dk * 64 + tx * 4];
            float aq[4] = {qa.x, qa.y, qa.z, qa.w};
            float bk[4] = {kb.x, kb.y, kb.z, kb.w};
#pragma unroll
            for (int i = 0; i < 4; i++)
#pragma unroll
                for (int j = 0; j < 4; j++)
                    s[i][j] = fmaf(aq[i], bk[j], s[i][j]);
        }

#pragma unroll
        for (int i = 0; i < 4; i++) {
            float mx = fmaxf(fmaxf(s[i][0], s[i][1]), fmaxf(s[i][2], s[i][3]));
            mx = fmaxf(mx, __shfl_xor_sync(0xffffffffu, mx, 1));
            mx = fmaxf(mx, __shfl_xor_sync(0xffffffffu, mx, 2));
            mx = fmaxf(mx, __shfl_xor_sync(0xffffffffu, mx, 4));
            mx = fmaxf(mx, __shfl_xor_sync(0xffffffffu, mx, 8));
            float mn   = fmaxf(mrow[i], mx);
            float corr = __expf(mrow[i] - mn);
            mrow[i] = mn;
            float sum = 0.f;
#pragma unroll
            for (int j = 0; j < 4; j++) {
                float p = __expf(s[i][j] - mn);
                s[i][j] = p;
                sum += p;
            }
            sum += __shfl_xor_sync(0xffffffffu, sum, 1);
            sum += __shfl_xor_sync(0xffffffffu, sum, 2);
            sum += __shfl_xor_sync(0xffffffffu, sum, 4);
            sum += __shfl_xor_sync(0xffffffffu, sum, 8);
            lrow[i] = lrow[i] * corr + sum;
#pragma unroll
            for (int j = 0; j < 4; j++) o[i][j] *= corr;
        }

#pragma unroll
        for (int j = 0; j < 4; j++)
#pragma unroll
            for (int i = 0; i < 4; i++)
                Ps[(tx * 4 + j) * PS_STRIDE + ty * 4 + i] = s[i][j];
        __syncthreads();

#pragma unroll 16
        for (int k = 0; k < BKV; ++k) {
            float4 pa = *(const float4*)&Ps[k * PS_STRIDE + ty * 4];
            float4 vb = *(const float4*)&Vs[k * 64 + tx * 4];
            float pp[4] = {pa.x, pa.y, pa.z, pa.w};
            float vv[4] = {vb.x, vb.y, vb.z, vb.w};
#pragma unroll
            for (int i = 0; i < 4; i++)
#pragma unroll
                for (int j = 0; j < 4; j++)
                    o[i][j] = fmaf(pp[i], vv[j], o[i][j]);
        }
    }

    float* Og = g_A + (size_t)b * Sc * Dc + (size_t)h * DKc;
#pragma unroll
    for (int i = 0; i < 4; i++) {
        float inv = 1.f / lrow[i];
        size_t row = (size_t)(q0 + ty * 4 + i);
        float4 cv;
        cv.x = o[i][0] * inv;
        cv.y = o[i][1] * inv;
        cv.z = o[i][2] * inv;
        cv.w = o[i][3] * inv;
        *(float4*)(Og + row * Dc + tx * 4) = cv;
    }
}

// ---------------------------------------------------------------------------
// Launch
// ---------------------------------------------------------------------------
extern "C" void kernel_launch(void* const* d_in, const int* in_sizes, int n_in,
                              void* d_out, int out_size)
{
    const float* q  = (const float*)d_in[0];
    const float* k  = (const float*)d_in[1];
    const float* v  = (const float*)d_in[2];
    const float* wq = (const float*)d_in[3];
    const float* bq = (const float*)d_in[4];
    const float* wk = (const float*)d_in[5];
    const float* bk = (const float*)d_in[6];
    const float* wv = (const float*)d_in[7];
    const float* bv = (const float*)d_in[8];
    const float* wo = (const float*)d_in[9];
    const float* bo = (const float*)d_in[10];
    float* out = (float*)d_out;

    float *pQ, *pK, *pV, *pA;
    __nv_bfloat16 *pXh, *pXl, *pWh, *pWl;
    cudaGetSymbolAddress((void**)&pQ, g_Q);
    cudaGetSymbolAddress((void**)&pK, g_K);
    cudaGetSymbolAddress((void**)&pV, g_V);
    cudaGetSymbolAddress((void**)&pA, g_A);
    cudaGetSymbolAddress((void**)&pXh, g_Xh);
    cudaGetSymbolAddress((void**)&pXl, g_Xl);
    cudaGetSymbolAddress((void**)&pWh, g_Wh);
    cudaGetSymbolAddress((void**)&pWl, g_Wl);

    const int attn_smem = ATTN_SMEM_FLOATS * sizeof(float);
    cudaFuncSetAttribute(attn_kernel, cudaFuncAttributeMaxDynamicSharedMemorySize,
                         attn_smem);

    const int n4 = MROWS * Dc / 4;
    dim3 cwgrid(Dc / 32, Dc / 32), cwblk(32, 8);
    dim3 ggrid(Dc / 128, MROWS / 128);   // (8, 64)

    // Q projection
    conv_wT_kernel<<<cwgrid, cwblk>>>(wq, pWh, pWl);
    conv_act_kernel<<<n4 / 256, 256>>>(q, pXh, pXl, n4);
    gemm_tc_kernel<<<ggrid, 256>>>(pXh, pXl, pWh, pWl, bq, pQ);
    // K projection
    conv_wT_kernel<<<cwgrid, cwblk>>>(wk, pWh, pWl);
    conv_act_kernel<<<n4 / 256, 256>>>(k, pXh, pXl, n4);
    gemm_tc_kernel<<<ggrid, 256>>>(pXh, pXl, pWh, pWl, bk, pK);
    // V projection
    conv_wT_kernel<<<cwgrid, cwblk>>>(wv, pWh, pWl);
    conv_act_kernel<<<n4 / 256, 256>>>(v, pXh, pXl, n4);
    gemm_tc_kernel<<<ggrid, 256>>>(pXh, pXl, pWh, pWl, bv, pV);

    // Attention (fp32)
    dim3 agrid(Sc / BQ, Bc * Hc);        // (32, 64)
    attn_kernel<<<agrid, 256, attn_smem>>>();

    // Output projection
    conv_wT_kernel<<<cwgrid, cwblk>>>(wo, pWh, pWl);
    conv_act_kernel<<<n4 / 256, 256>>>(pA, pXh, pXl, n4);
    gemm_tc_kernel<<<ggrid, 256>>>(pXh, pXl, pWh, pWl, bo, out);
}

// round 4
// speedup vs baseline: 2.3165x; 1.8554x over previous
#include <cuda_runtime.h>
#include <cuda_bf16.h>
#include <math.h>
#include <stdint.h>

// Problem constants
#define Bc 4
#define Sc 2048
#define Dc 1024
#define Hc 16
#define DKc 64
#define MROWS (Bc * Sc)   // 8192

// fp32 scratch
__device__ float g_Q[MROWS * Dc];
__device__ float g_K[MROWS * Dc];
__device__ float g_V[MROWS * Dc];
__device__ float g_A[MROWS * Dc];
// bf16 split scratch for GEMMs
__device__ __nv_bfloat16 g_Xh[MROWS * Dc];
__device__ __nv_bfloat16 g_Xl[MROWS * Dc];
__device__ __nv_bfloat16 g_Wh[Dc * Dc];
__device__ __nv_bfloat16 g_Wl[Dc * Dc];
// bf16 split scratch for attention
__device__ __nv_bfloat16 g_Qh[MROWS * Dc];
__device__ __nv_bfloat16 g_Ql[MROWS * Dc];
__device__ __nv_bfloat16 g_Kh[MROWS * Dc];
__device__ __nv_bfloat16 g_Kl[MROWS * Dc];
__device__ __nv_bfloat16 g_VTh[MROWS * Dc];  // [bh][dk][s]
__device__ __nv_bfloat16 g_VTl[MROWS * Dc];

// ---------------------------------------------------------------------------
// Warp-MMA helpers
// ---------------------------------------------------------------------------
__device__ __forceinline__ uint32_t smem_u32(const void* p) {
    uint32_t a;
    asm("{ .reg .u64 t; cvta.to.shared.u64 t, %1; cvt.u32.u64 %0, t; }"
        : "=r"(a) : "l"(p));
    return a;
}

__device__ __forceinline__ void ldsm_x4(uint32_t& r0, uint32_t& r1,
                                        uint32_t& r2, uint32_t& r3,
                                        uint32_t addr) {
    asm volatile("ldmatrix.sync.aligned.m8n8.x4.shared.b16 {%0,%1,%2,%3}, [%4];"
                 : "=r"(r0), "=r"(r1), "=r"(r2), "=r"(r3) : "r"(addr));
}

__device__ __forceinline__ void mma_bf16(float* c, const uint32_t* a,
                                         uint32_t b0, uint32_t b1) {
    asm volatile(
        "mma.sync.aligned.m16n8k16.row.col.f32.bf16.bf16.f32 "
        "{%0,%1,%2,%3}, {%4,%5,%6,%7}, {%8,%9}, {%0,%1,%2,%3};"
        : "+f"(c[0]), "+f"(c[1]), "+f"(c[2]), "+f"(c[3])
        : "r"(a[0]), "r"(a[1]), "r"(a[2]), "r"(a[3]), "r"(b0), "r"(b1));
}

__device__ __forceinline__ uint32_t pack_bf16(float a, float b) {
    __nv_bfloat16 ha = __float2bfloat16(a);
    __nv_bfloat16 hb = __float2bfloat16(b);
    return (uint32_t)__bfloat16_as_ushort(ha) |
           ((uint32_t)__bfloat16_as_ushort(hb) << 16);
}

// ---------------------------------------------------------------------------
// fp32 -> (bf16 hi, bf16 lo) elementwise split (with scale)
// ---------------------------------------------------------------------------
__global__ void __launch_bounds__(256) conv_act_kernel(
    const float* __restrict__ X,
    __nv_bfloat16* __restrict__ H, __nv_bfloat16* __restrict__ L,
    int n4, float scale)
{
    int i = blockIdx.x * blockDim.x + threadIdx.x;
    if (i >= n4) return;
    float4 v = ((const float4*)X)[i];
    float f[4] = {v.x * scale, v.y * scale, v.z * scale, v.w * scale};
    uint32_t hp[2], lp[2];
#pragma unroll
    for (int j = 0; j < 2; j++) {
        __nv_bfloat16 h0 = __float2bfloat16(f[2*j]);
        __nv_bfloat16 h1 = __float2bfloat16(f[2*j+1]);
        __nv_bfloat16 l0 = __float2bfloat16(f[2*j]   - __bfloat162float(h0));
        __nv_bfloat16 l1 = __float2bfloat16(f[2*j+1] - __bfloat162float(h1));
        hp[j] = (uint32_t)__bfloat16_as_ushort(h0) | ((uint32_t)__bfloat16_as_ushort(h1) << 16);
        lp[j] = (uint32_t)__bfloat16_as_ushort(l0) | ((uint32_t)__bfloat16_as_ushort(l1) << 16);
    }
    ((uint2*)H)[i] = make_uint2(hp[0], hp[1]);
    ((uint2*)L)[i] = make_uint2(lp[0], lp[1]);
}

// ---------------------------------------------------------------------------
// Weight [K,N] -> transposed split [N,K] hi/lo
// ---------------------------------------------------------------------------
__global__ void __launch_bounds__(256) conv_wT_kernel(
    const float* __restrict__ W,
    __nv_bfloat16* __restrict__ Th, __nv_bfloat16* __restrict__ Tl)
{
    __shared__ float t[32][33];
    int n0 = blockIdx.x * 32;
    int k0 = blockIdx.y * 32;
    int tx = threadIdx.x, ty = threadIdx.y;
#pragma unroll
    for (int i = 0; i < 4; i++)
        t[ty + 8*i][tx] = W[(size_t)(k0 + ty + 8*i) * Dc + n0 + tx];
    __syncthreads();
#pragma unroll
    for (int i = 0; i < 4; i++) {
        float v = t[tx][ty + 8*i];
        __nv_bfloat16 h = __float2bfloat16(v);
        __nv_bfloat16 l = __float2bfloat16(v - __bfloat162float(h));
        size_t idx = (size_t)(n0 + ty + 8*i) * Dc + k0 + tx;
        Th[idx] = h;
        Tl[idx] = l;
    }
}

// ---------------------------------------------------------------------------
// V [b*S+s][h*64+dk] -> VT split [bh][dk][s] hi/lo (transpose per head)
// grid (S/32, 2, 64bh), block (32,8)
// ---------------------------------------------------------------------------
__global__ void __launch_bounds__(256) conv_vT_kernel(
    const float* __restrict__ V,
    __nv_bfloat16* __restrict__ Th, __nv_bfloat16* __restrict__ Tl)
{
    __shared__ float t[32][33];
    const int s0 = blockIdx.x * 32;
    const int d0 = blockIdx.y * 32;
    const int bh = blockIdx.z;
    const int b  = bh >> 4, h = bh & 15;
    const int tx = threadIdx.x, ty = threadIdx.y;
#pragma unroll
    for (int i = 0; i < 4; i++)
        t[ty + 8*i][tx] = V[(size_t)(b * Sc + s0 + ty + 8*i) * Dc + h * DKc + d0 + tx];
    __syncthreads();
#pragma unroll
    for (int i = 0; i < 4; i++) {
        float v = t[tx][ty + 8*i];
        __nv_bfloat16 hh = __float2bfloat16(v);
        __nv_bfloat16 ll = __float2bfloat16(v - __bfloat162float(hh));
        size_t idx = (size_t)bh * (DKc * Sc) + (size_t)(d0 + ty + 8*i) * Sc + s0 + tx;
        Th[idx] = hh;
        Tl[idx] = ll;
    }
}

// ---------------------------------------------------------------------------
// mma.sync bf16 split-3 GEMM (unchanged from R3)
// ---------------------------------------------------------------------------
__global__ void __launch_bounds__(256) gemm_tc_kernel(
    const __nv_bfloat16* __restrict__ Ah, const __nv_bfloat16* __restrict__ Al,
    const __nv_bfloat16* __restrict__ Bh, const __nv_bfloat16* __restrict__ Bl,
    const float* __restrict__ bias, float* __restrict__ C)
{
    __shared__ __align__(128) char smem[32768];
    const uint32_t sb = smem_u32(smem);

    const int tid    = threadIdx.x;
    const int lane   = tid & 31;
    const int wid    = tid >> 5;
    const int warp_m = wid >> 1;
    const int warp_n = wid & 1;
    const int m0     = blockIdx.y * 128;
    const int n0     = blockIdx.x * 128;

    float acc[2][8][4];
#pragma unroll
    for (int mt = 0; mt < 2; mt++)
#pragma unroll
        for (int nt = 0; nt < 8; nt++)
#pragma unroll
            for (int e = 0; e < 4; e++) acc[mt][nt][e] = 0.f;

    uint32_t aAddr[2][2], bAddr[4][2];
#pragma unroll
    for (int mt = 0; mt < 2; mt++)
#pragma unroll
        for (int ks = 0; ks < 2; ks++) {
            int row = warp_m * 32 + mt * 16 + (lane & 15);
            int ch  = ks * 2 + (lane >> 4);
            aAddr[mt][ks] = sb + row * 64 + ((ch ^ ((row >> 1) & 3)) << 4);
        }
#pragma unroll
    for (int j = 0; j < 4; j++)
#pragma unroll
        for (int ks = 0; ks < 2; ks++) {
            int row = warp_n * 64 + j * 16 + ((lane >> 4) << 3) + (lane & 7);
            int ch  = ks * 2 + ((lane >> 3) & 1);
            bAddr[j][ks] = sb + 16384 + row * 64 + ((ch ^ ((row >> 1) & 3)) << 4);
        }

    for (int kt = 0; kt < Dc / 32; ++kt) {
        const int k0 = kt * 32;
        __syncthreads();
        const __nv_bfloat16* gsrc[4] = {Ah, Al, Bh, Bl};
        const int rowbase[4] = {m0, m0, n0, n0};
#pragma unroll
        for (int i = 0; i < 8; ++i) {
            const int t  = i >> 1;
            const int c  = tid + (i & 1) * 256;
            const int row = c >> 2;
            const int ch  = c & 3;
            uint32_t so = (uint32_t)(t * 8192 + row * 64 +
                                     ((ch ^ ((row >> 1) & 3)) << 4));
            size_t gi = (((size_t)(rowbase[t] + row)) << 10) + k0 + ch * 8;
            *(uint4*)(smem + so) = *(const uint4*)(gsrc[t] + gi);
        }
        __syncthreads();

#pragma unroll
        for (int ks = 0; ks < 2; ++ks) {
            uint32_t ah[2][4], al[2][4];
#pragma unroll
            for (int mt = 0; mt < 2; mt++) {
                ldsm_x4(ah[mt][0], ah[mt][1], ah[mt][2], ah[mt][3], aAddr[mt][ks]);
                ldsm_x4(al[mt][0], al[mt][1], al[mt][2], al[mt][3], aAddr[mt][ks] + 8192);
            }
#pragma unroll
            for (int j = 0; j < 4; ++j) {
                uint32_t b4[4];
                ldsm_x4(b4[0], b4[1], b4[2], b4[3], bAddr[j][ks]);
#pragma unroll
                for (int mt = 0; mt < 2; mt++) {
                    mma_bf16(acc[mt][2*j],   ah[mt], b4[0], b4[1]);
                    mma_bf16(acc[mt][2*j+1], ah[mt], b4[2], b4[3]);
                    mma_bf16(acc[mt][2*j],   al[mt], b4[0], b4[1]);
                    mma_bf16(acc[mt][2*j+1], al[mt], b4[2], b4[3]);
                }
                ldsm_x4(b4[0], b4[1], b4[2], b4[3], bAddr[j][ks] + 8192);
#pragma unroll
                for (int mt = 0; mt < 2; mt++) {
                    mma_bf16(acc[mt][2*j],   ah[mt], b4[0], b4[1]);
                    mma_bf16(acc[mt][2*j+1], ah[mt], b4[2], b4[3]);
                }
            }
        }
    }

    const int trow = lane >> 2;
    const int tcol = (lane & 3) * 2;
#pragma unroll
    for (int mt = 0; mt < 2; mt++) {
        const int r0 = m0 + warp_m * 32 + mt * 16 + trow;
#pragma unroll
        for (int nt = 0; nt < 8; nt++) {
            const int col = n0 + warp_n * 64 + nt * 8 + tcol;
            float2 b2 = *(const float2*)(bias + col);
            float2 v0 = {acc[mt][nt][0] + b2.x, acc[mt][nt][1] + b2.y};
            float2 v1 = {acc[mt][nt][2] + b2.x, acc[mt][nt][3] + b2.y};
            *(float2*)(C + (size_t)r0 * Dc + col)       = v0;
            *(float2*)(C + (size_t)(r0 + 8) * Dc + col) = v1;
        }
    }
}

// ---------------------------------------------------------------------------
// Tensor-core flash attention.
// BQ=128 (8 warps x 16 rows), BKV=64, DK=64.
// S = Qh.Kh + Ql.Kh + Qh.Kl ; O = Ph.Vh + Pl.Vh + Ph.Vl (split-3 both).
// Smem: Kh(8K) Kl(8K) VTh(8K) VTl(8K); rows 128B, swizzle ch^(row&7).
// ---------------------------------------------------------------------------
__global__ void __launch_bounds__(256) attn_tc_kernel()
{
    __shared__ __align__(128) char smem[32768];
    const uint32_t sb = smem_u32(smem);

    const int tid  = threadIdx.x;
    const int lane = tid & 31;
    const int wid  = tid >> 5;
    const int qt   = blockIdx.x;
    const int bh   = blockIdx.y;
    const int b    = bh >> 4, h = bh & 15;
    const int q0   = qt * 128;
    const int grp  = lane >> 2;
    const int lc2  = (lane & 3) * 2;

    // Load Q fragments (hi/lo), resident for whole kernel.
    uint32_t qfh[4][4], qfl[4][4];
    {
        const size_t rbase = (size_t)(b * Sc + q0 + wid * 16 + grp) * Dc + h * DKc;
#pragma unroll
        for (int ks = 0; ks < 4; ++ks)
#pragma unroll
            for (int r2 = 0; r2 < 2; ++r2)
#pragma unroll
                for (int kh = 0; kh < 2; ++kh) {
                    size_t off = rbase + (size_t)r2 * 8 * Dc + ks * 16 + kh * 8 + lc2;
                    qfh[ks][r2 + 2*kh] = *(const uint32_t*)(g_Qh + off);
                    qfl[ks][r2 + 2*kh] = *(const uint32_t*)(g_Ql + off);
                }
    }

    // ldsm address bases (row part is kt-invariant).
    const int rowsm = ((lane >> 4) << 3) + (lane & 7);
    const int chx   = ((lane >> 3) & 1);
    const int l7    = lane & 7;
    const uint32_t baseK = sb + rowsm * 128;
    const uint32_t baseV = sb + 16384 + rowsm * 128;

    float m[2] = {-INFINITY, -INFINITY};
    float l[2] = {0.f, 0.f};
    float O[4][2][4];
#pragma unroll
    for (int jv = 0; jv < 4; jv++)
#pragma unroll
        for (int t = 0; t < 2; t++)
#pragma unroll
            for (int e = 0; e < 4; e++) O[jv][t][e] = 0.f;

    const __nv_bfloat16* Khg  = g_Kh  + (size_t)b * Sc * Dc + h * DKc;
    const __nv_bfloat16* Klg  = g_Kl  + (size_t)b * Sc * Dc + h * DKc;
    const __nv_bfloat16* VThg = g_VTh + (size_t)bh * DKc * Sc;
    const __nv_bfloat16* VTlg = g_VTl + (size_t)bh * DKc * Sc;

    for (int kt = 0; kt < Sc / 64; ++kt) {
        const int k0 = kt * 64;
        __syncthreads();
        // Stage K hi/lo ([key][dk]) and VT hi/lo ([dk][s]) tiles: 64x128B each.
#pragma unroll
        for (int i = 0; i < 8; ++i) {
            const int t  = i >> 1;
            const int c  = tid + (i & 1) * 256;   // 0..511
            const int row = c >> 3;
            const int ch  = c & 7;
            const uint32_t so = (uint32_t)(t * 8192 + row * 128 + ((ch ^ (row & 7)) << 4));
            const __nv_bfloat16* src;
            size_t gi;
            if (t < 2) {
                src = (t == 0) ? Khg : Klg;
                gi  = (size_t)(k0 + row) * Dc + ch * 8;
            } else {
                src = (t == 2) ? VThg : VTlg;
                gi  = (size_t)row * Sc + k0 + ch * 8;
            }
            *(uint4*)(smem + so) = *(const uint4*)(src + gi);
        }
        __syncthreads();

        // S = Q.K^T (3 split terms)
        float S[4][2][4];
#pragma unroll
        for (int j = 0; j < 4; j++)
#pragma unroll
            for (int t = 0; t < 2; t++)
#pragma unroll
                for (int e = 0; e < 4; e++) S[j][t][e] = 0.f;

#pragma unroll
        for (int ks = 0; ks < 4; ++ks)
#pragma unroll
            for (int j = 0; j < 4; ++j) {
                uint32_t b4[4];
                uint32_t a0 = baseK + j * 2048 + (((ks * 2 + chx) ^ l7) << 4);
                ldsm_x4(b4[0], b4[1], b4[2], b4[3], a0);
                mma_bf16(S[j][0], qfh[ks], b4[0], b4[1]);
                mma_bf16(S[j][1], qfh[ks], b4[2], b4[3]);
                mma_bf16(S[j][0], qfl[ks], b4[0], b4[1]);
                mma_bf16(S[j][1], qfl[ks], b4[2], b4[3]);
                ldsm_x4(b4[0], b4[1], b4[2], b4[3], a0 + 8192);
                mma_bf16(S[j][0], qfh[ks], b4[0], b4[1]);
                mma_bf16(S[j][1], qfh[ks], b4[2], b4[3]);
            }

        // Online softmax (rows grp and grp+8 per lane).
#pragma unroll
        for (int r2 = 0; r2 < 2; ++r2) {
            float mx = -INFINITY;
#pragma unroll
            for (int j = 0; j < 4; j++)
#pragma unroll
                for (int t = 0; t < 2; t++)
                    mx = fmaxf(mx, fmaxf(S[j][t][2*r2], S[j][t][2*r2+1]));
            mx = fmaxf(mx, __shfl_xor_sync(0xffffffffu, mx, 1));
            mx = fmaxf(mx, __shfl_xor_sync(0xffffffffu, mx, 2));
            float mn   = fmaxf(m[r2], mx);
            float corr = __expf(m[r2] - mn);
            m[r2] = mn;
            float sum = 0.f;
#pragma unroll
            for (int j = 0; j < 4; j++)
#pragma unroll
                for (int t = 0; t < 2; t++) {
                    float p0 = __expf(S[j][t][2*r2]   - mn);
                    float p1 = __expf(S[j][t][2*r2+1] - mn);
                    S[j][t][2*r2]   = p0;
                    S[j][t][2*r2+1] = p1;
                    sum += p0 + p1;
                }
            sum += __shfl_xor_sync(0xffffffffu, sum, 1);
            sum += __shfl_xor_sync(0xffffffffu, sum, 2);
            l[r2] = l[r2] * corr + sum;
#pragma unroll
            for (int jv = 0; jv < 4; jv++)
#pragma unroll
                for (int t = 0; t < 2; t++) {
                    O[jv][t][2*r2]   *= corr;
                    O[jv][t][2*r2+1] *= corr;
                }
        }

        // O += P.V (3 split terms); P frags built from S accumulators.
#pragma unroll
        for (int ksv = 0; ksv < 4; ++ksv) {
            uint32_t ph[4], pl[4];
#pragma unroll
            for (int t = 0; t < 2; t++)
#pragma unroll
                for (int r2 = 0; r2 < 2; r2++) {
                    float p0 = S[ksv][t][2*r2];
                    float p1 = S[ksv][t][2*r2+1];
                    uint32_t hp = pack_bf16(p0, p1);
                    __nv_bfloat16 h0 = __ushort_as_bfloat16((unsigned short)(hp & 0xffff));
                    __nv_bfloat16 h1 = __ushort_as_bfloat16((unsigned short)(hp >> 16));
                    uint32_t lp = pack_bf16(p0 - __bfloat162float(h0),
                                            p1 - __bfloat162float(h1));
                    ph[r2 + 2*t] = hp;
                    pl[r2 + 2*t] = lp;
                }
#pragma unroll
            for (int jv = 0; jv < 4; ++jv) {
                uint32_t b4[4];
                uint32_t a0 = baseV + jv * 2048 + (((ksv * 2 + chx) ^ l7) << 4);
                ldsm_x4(b4[0], b4[1], b4[2], b4[3], a0);
                mma_bf16(O[jv][0], ph, b4[0], b4[1]);
                mma_bf16(O[jv][1], ph, b4[2], b4[3]);
                mma_bf16(O[jv][0], pl, b4[0], b4[1]);
                mma_bf16(O[jv][1], pl, b4[2], b4[3]);
                ldsm_x4(b4[0], b4[1], b4[2], b4[3], a0 + 8192);
                mma_bf16(O[jv][0], ph, b4[0], b4[1]);
                mma_bf16(O[jv][1], ph, b4[2], b4[3]);
            }
        }
    }

    // Epilogue: normalize and write.
    const float inv0 = 1.f / l[0];
    const float inv1 = 1.f / l[1];
    float* Og = g_A + (size_t)b * Sc * Dc + h * DKc;
    const int r0 = q0 + wid * 16 + grp;
#pragma unroll
    for (int jv = 0; jv < 4; ++jv)
#pragma unroll
        for (int t = 0; t < 2; ++t) {
            const int col = jv * 16 + t * 8 + lc2;
            float2 v0 = {O[jv][t][0] * inv0, O[jv][t][1] * inv0};
            float2 v1 = {O[jv][t][2] * inv1, O[jv][t][3] * inv1};
            *(float2*)(Og + (size_t)r0 * Dc + col)       = v0;
            *(float2*)(Og + (size_t)(r0 + 8) * Dc + col) = v1;
        }
}

// ---------------------------------------------------------------------------
// Launch
// ---------------------------------------------------------------------------
extern "C" void kernel_launch(void* const* d_in, const int* in_sizes, int n_in,
                              void* d_out, int out_size)
{
    const float* q  = (const float*)d_in[0];
    const float* k  = (const float*)d_in[1];
    const float* v  = (const float*)d_in[2];
    const float* wq = (const float*)d_in[3];
    const float* bq = (const float*)d_in[4];
    const float* wk = (const float*)d_in[5];
    const float* bk = (const float*)d_in[6];
    const float* wv = (const float*)d_in[7];
    const float* bv = (const float*)d_in[8];
    const float* wo = (const float*)d_in[9];
    const float* bo = (const float*)d_in[10];
    float* out = (float*)d_out;

    float *pQ, *pK, *pV, *pA;
    __nv_bfloat16 *pXh, *pXl, *pWh, *pWl, *pQh, *pQl, *pKh, *pKl, *pVTh, *pVTl;
    cudaGetSymbolAddress((void**)&pQ, g_Q);
    cudaGetSymbolAddress((void**)&pK, g_K);
    cudaGetSymbolAddress((void**)&pV, g_V);
    cudaGetSymbolAddress((void**)&pA, g_A);
    cudaGetSymbolAddress((void**)&pXh, g_Xh);
    cudaGetSymbolAddress((void**)&pXl, g_Xl);
    cudaGetSymbolAddress((void**)&pWh, g_Wh);
    cudaGetSymbolAddress((void**)&pWl, g_Wl);
    cudaGetSymbolAddress((void**)&pQh, g_Qh);
    cudaGetSymbolAddress((void**)&pQl, g_Ql);
    cudaGetSymbolAddress((void**)&pKh, g_Kh);
    cudaGetSymbolAddress((void**)&pKl, g_Kl);
    cudaGetSymbolAddress((void**)&pVTh, g_VTh);
    cudaGetSymbolAddress((void**)&pVTl, g_VTl);

    const int n4 = MROWS * Dc / 4;
    dim3 cwgrid(Dc / 32, Dc / 32), cwblk(32, 8);
    dim3 ggrid(Dc / 128, MROWS / 128);

    // Projections
    conv_wT_kernel<<<cwgrid, cwblk>>>(wq, pWh, pWl);
    conv_act_kernel<<<n4 / 256, 256>>>(q, pXh, pXl, n4, 1.f);
    gemm_tc_kernel<<<ggrid, 256>>>(pXh, pXl, pWh, pWl, bq, pQ);
    conv_wT_kernel<<<cwgrid, cwblk>>>(wk, pWh, pWl);
    conv_act_kernel<<<n4 / 256, 256>>>(k, pXh, pXl, n4, 1.f);
    gemm_tc_kernel<<<ggrid, 256>>>(pXh, pXl, pWh, pWl, bk, pK);
    conv_wT_kernel<<<cwgrid, cwblk>>>(wv, pWh, pWl);
    conv_act_kernel<<<n4 / 256, 256>>>(v, pXh, pXl, n4, 1.f);
    gemm_tc_kernel<<<ggrid, 256>>>(pXh, pXl, pWh, pWl, bv, pV);

    // Attention operand conversions
    conv_act_kernel<<<n4 / 256, 256>>>(pQ, pQh, pQl, n4, 0.125f);
    conv_act_kernel<<<n4 / 256, 256>>>(pK, pKh, pKl, n4, 1.f);
    dim3 vtgrid(Sc / 32, DKc / 32, Bc * Hc);
    conv_vT_kernel<<<vtgrid, cwblk>>>(pV, pVTh, pVTl);

    // Tensor-core attention
    dim3 agrid(Sc / 128, Bc * Hc);   // (16, 64)
    attn_tc_kernel<<<agrid, 256>>>();

    // Output projection
    conv_wT_kernel<<<cwgrid, cwblk>>>(wo, pWh, pWl);
    conv_act_kernel<<<n4 / 256, 256>>>(pA, pXh, pXl, n4, 1.f);
    gemm_tc_kernel<<<ggrid, 256>>>(pXh, pXl, pWh, pWl, bo, out);
}

// round 5
// speedup vs baseline: 3.1449x; 1.3576x over previous
#include <cuda_runtime.h>
#include <cuda_bf16.h>
#include <math.h>
#include <stdint.h>

// Problem constants
#define Bc 4
#define Sc 2048
#define Dc 1024
#define Hc 16
#define DKc 64
#define MROWS (Bc * Sc)   // 8192

// fp32 scratch
__device__ float g_V[MROWS * Dc];
// bf16 split scratch
__device__ __nv_bfloat16 g_Xh[MROWS * Dc];
__device__ __nv_bfloat16 g_Xl[MROWS * Dc];
__device__ __nv_bfloat16 g_Wh[Dc * Dc];
__device__ __nv_bfloat16 g_Wl[Dc * Dc];
__device__ __nv_bfloat16 g_Qh[MROWS * Dc];
__device__ __nv_bfloat16 g_Ql[MROWS * Dc];
__device__ __nv_bfloat16 g_Kh[MROWS * Dc];
__device__ __nv_bfloat16 g_Kl[MROWS * Dc];
__device__ __nv_bfloat16 g_VTh[MROWS * Dc];  // [bh][dk][s]
__device__ __nv_bfloat16 g_VTl[MROWS * Dc];

// ---------------------------------------------------------------------------
// Helpers
// ---------------------------------------------------------------------------
__device__ __forceinline__ uint32_t smem_u32(const void* p) {
    uint32_t a;
    asm("{ .reg .u64 t; cvta.to.shared.u64 t, %1; cvt.u32.u64 %0, t; }"
        : "=r"(a) : "l"(p));
    return a;
}

__device__ __forceinline__ void ldsm_x4(uint32_t& r0, uint32_t& r1,
                                        uint32_t& r2, uint32_t& r3,
                                        uint32_t addr) {
    asm volatile("ldmatrix.sync.aligned.m8n8.x4.shared.b16 {%0,%1,%2,%3}, [%4];"
                 : "=r"(r0), "=r"(r1), "=r"(r2), "=r"(r3) : "r"(addr));
}

__device__ __forceinline__ void mma_bf16(float* c, const uint32_t* a,
                                         uint32_t b0, uint32_t b1) {
    asm volatile(
        "mma.sync.aligned.m16n8k16.row.col.f32.bf16.bf16.f32 "
        "{%0,%1,%2,%3}, {%4,%5,%6,%7}, {%8,%9}, {%0,%1,%2,%3};"
        : "+f"(c[0]), "+f"(c[1]), "+f"(c[2]), "+f"(c[3])
        : "r"(a[0]), "r"(a[1]), "r"(a[2]), "r"(a[3]), "r"(b0), "r"(b1));
}

__device__ __forceinline__ uint32_t pack_bf16(float a, float b) {
    __nv_bfloat16 ha = __float2bfloat16(a);
    __nv_bfloat16 hb = __float2bfloat16(b);
    return (uint32_t)__bfloat16_as_ushort(ha) |
           ((uint32_t)__bfloat16_as_ushort(hb) << 16);
}

__device__ __forceinline__ void split2(float a, float b,
                                       uint32_t& hi, uint32_t& lo) {
    __nv_bfloat16 ha = __float2bfloat16(a);
    __nv_bfloat16 hb = __float2bfloat16(b);
    hi = (uint32_t)__bfloat16_as_ushort(ha) |
         ((uint32_t)__bfloat16_as_ushort(hb) << 16);
    lo = pack_bf16(a - __bfloat162float(ha), b - __bfloat162float(hb));
}

__device__ __forceinline__ void cp16(uint32_t dst, const void* src) {
    asm volatile("cp.async.cg.shared.global [%0], [%1], 16;"
                 :: "r"(dst), "l"(src));
}
#define CP_COMMIT() asm volatile("cp.async.commit_group;" ::: "memory")
#define CP_WAIT(n)  asm volatile("cp.async.wait_group %0;" :: "n"(n) : "memory")

// ---------------------------------------------------------------------------
// fp32 -> (bf16 hi, bf16 lo) elementwise split (with scale)
// ---------------------------------------------------------------------------
__global__ void __launch_bounds__(256) conv_act_kernel(
    const float* __restrict__ X,
    __nv_bfloat16* __restrict__ H, __nv_bfloat16* __restrict__ L,
    int n4, float scale)
{
    int i = blockIdx.x * blockDim.x + threadIdx.x;
    if (i >= n4) return;
    float4 v = ((const float4*)X)[i];
    float f[4] = {v.x * scale, v.y * scale, v.z * scale, v.w * scale};
    uint32_t hp[2], lp[2];
#pragma unroll
    for (int j = 0; j < 2; j++) split2(f[2*j], f[2*j+1], hp[j], lp[j]);
    ((uint2*)H)[i] = make_uint2(hp[0], hp[1]);
    ((uint2*)L)[i] = make_uint2(lp[0], lp[1]);
}

// ---------------------------------------------------------------------------
// Weight [K,N] -> transposed split [N,K] hi/lo
// ---------------------------------------------------------------------------
__global__ void __launch_bounds__(256) conv_wT_kernel(
    const float* __restrict__ W,
    __nv_bfloat16* __restrict__ Th, __nv_bfloat16* __restrict__ Tl)
{
    __shared__ float t[32][33];
    int n0 = blockIdx.x * 32;
    int k0 = blockIdx.y * 32;
    int tx = threadIdx.x, ty = threadIdx.y;
#pragma unroll
    for (int i = 0; i < 4; i++)
        t[ty + 8*i][tx] = W[(size_t)(k0 + ty + 8*i) * Dc + n0 + tx];
    __syncthreads();
#pragma unroll
    for (int i = 0; i < 4; i++) {
        float v = t[tx][ty + 8*i];
        __nv_bfloat16 h = __float2bfloat16(v);
        __nv_bfloat16 l = __float2bfloat16(v - __bfloat162float(h));
        size_t idx = (size_t)(n0 + ty + 8*i) * Dc + k0 + tx;
        Th[idx] = h;
        Tl[idx] = l;
    }
}

// ---------------------------------------------------------------------------
// V [b*S+s][h*64+dk] -> VT split [bh][dk][s] hi/lo
// ---------------------------------------------------------------------------
__global__ void __launch_bounds__(256) conv_vT_kernel(
    const float* __restrict__ V,
    __nv_bfloat16* __restrict__ Th, __nv_bfloat16* __restrict__ Tl)
{
    __shared__ float t[32][33];
    const int s0 = blockIdx.x * 32;
    const int d0 = blockIdx.y * 32;
    const int bh = blockIdx.z;
    const int b  = bh >> 4, h = bh & 15;
    const int tx = threadIdx.x, ty = threadIdx.y;
#pragma unroll
    for (int i = 0; i < 4; i++)
        t[ty + 8*i][tx] = V[(size_t)(b * Sc + s0 + ty + 8*i) * Dc + h * DKc + d0 + tx];
    __syncthreads();
#pragma unroll
    for (int i = 0; i < 4; i++) {
        float v = t[tx][ty + 8*i];
        __nv_bfloat16 hh = __float2bfloat16(v);
        __nv_bfloat16 ll = __float2bfloat16(v - __bfloat162float(hh));
        size_t idx = (size_t)bh * (DKc * Sc) + (size_t)(d0 + ty + 8*i) * Sc + s0 + tx;
        Th[idx] = hh;
        Tl[idx] = ll;
    }
}

// ---------------------------------------------------------------------------
// Double-buffered mma.sync split-3 GEMM.
// C = (Ah+Al)[M,K] @ (Bh+Bl)[N,K]^T + bias, output fp32 OR split bf16.
// Tile 128x128, BK=32, 8 warps. Dynamic smem: 2 x 32KB.
// ---------------------------------------------------------------------------
__global__ void __launch_bounds__(256) gemm_tc_kernel(
    const __nv_bfloat16* __restrict__ Ah, const __nv_bfloat16* __restrict__ Al,
    const __nv_bfloat16* __restrict__ Bh, const __nv_bfloat16* __restrict__ Bl,
    const float* __restrict__ bias,
    float* __restrict__ Cf,
    __nv_bfloat16* __restrict__ Ch, __nv_bfloat16* __restrict__ Cl,
    float oscale)
{
    extern __shared__ __align__(128) char smem[];
    const uint32_t sb = smem_u32(smem);

    const int tid    = threadIdx.x;
    const int lane   = tid & 31;
    const int wid    = tid >> 5;
    const int warp_m = wid >> 1;
    const int warp_n = wid & 1;
    const int m0     = blockIdx.y * 128;
    const int n0     = blockIdx.x * 128;

    float acc[2][8][4];
#pragma unroll
    for (int mt = 0; mt < 2; mt++)
#pragma unroll
        for (int nt = 0; nt < 8; nt++)
#pragma unroll
            for (int e = 0; e < 4; e++) acc[mt][nt][e] = 0.f;

    uint32_t aAddr[2][2], bAddr[4][2];
#pragma unroll
    for (int mt = 0; mt < 2; mt++)
#pragma unroll
        for (int ks = 0; ks < 2; ks++) {
            int row = warp_m * 32 + mt * 16 + (lane & 15);
            int ch  = ks * 2 + (lane >> 4);
            aAddr[mt][ks] = sb + row * 64 + ((ch ^ ((row >> 1) & 3)) << 4);
        }
#pragma unroll
    for (int j = 0; j < 4; j++)
#pragma unroll
        for (int ks = 0; ks < 2; ks++) {
            int row = warp_n * 64 + j * 16 + ((lane >> 4) << 3) + (lane & 7);
            int ch  = ks * 2 + ((lane >> 3) & 1);
            bAddr[j][ks] = sb + 16384 + row * 64 + ((ch ^ ((row >> 1) & 3)) << 4);
        }

    // Per-thread staging addresses (stage-invariant parts).
    const int c0   = tid;             // chunk ids c0 and c0+256
    const __nv_bfloat16* gsrc[4] = {Ah, Al, Bh, Bl};
    const int rowbase[4] = {m0, m0, n0, n0};

    auto stage = [&](int kt, int buf) {
        const int k0 = kt * 32;
        const uint32_t bo = sb + (buf << 15);
#pragma unroll
        for (int i = 0; i < 8; ++i) {
            const int t   = i >> 1;
            const int c   = c0 + (i & 1) * 256;
            const int row = c >> 2;
            const int ch  = c & 3;
            uint32_t so = (uint32_t)(t * 8192 + row * 64 +
                                     ((ch ^ ((row >> 1) & 3)) << 4));
            size_t gi = (((size_t)(rowbase[t] + row)) << 10) + k0 + ch * 8;
            cp16(bo + so, gsrc[t] + gi);
        }
        CP_COMMIT();
    };

    stage(0, 0);

    for (int kt = 0; kt < Dc / 32; ++kt) {
        const bool has_next = (kt + 1) < (Dc / 32);
        if (has_next) stage(kt + 1, (kt + 1) & 1);
        if (has_next) CP_WAIT(1); else CP_WAIT(0);
        __syncthreads();

        const uint32_t bo = (uint32_t)((kt & 1) << 15);
#pragma unroll
        for (int ks = 0; ks < 2; ++ks) {
            uint32_t ah[2][4], al[2][4];
#pragma unroll
            for (int mt = 0; mt < 2; mt++) {
                ldsm_x4(ah[mt][0], ah[mt][1], ah[mt][2], ah[mt][3], aAddr[mt][ks] + bo);
                ldsm_x4(al[mt][0], al[mt][1], al[mt][2], al[mt][3], aAddr[mt][ks] + bo + 8192);
            }
#pragma unroll
            for (int j = 0; j < 4; ++j) {
                uint32_t b4[4];
                ldsm_x4(b4[0], b4[1], b4[2], b4[3], bAddr[j][ks] + bo);
#pragma unroll
                for (int mt = 0; mt < 2; mt++) {
                    mma_bf16(acc[mt][2*j],   ah[mt], b4[0], b4[1]);
                    mma_bf16(acc[mt][2*j+1], ah[mt], b4[2], b4[3]);
                    mma_bf16(acc[mt][2*j],   al[mt], b4[0], b4[1]);
                    mma_bf16(acc[mt][2*j+1], al[mt], b4[2], b4[3]);
                }
                ldsm_x4(b4[0], b4[1], b4[2], b4[3], bAddr[j][ks] + bo + 8192);
#pragma unroll
                for (int mt = 0; mt < 2; mt++) {
                    mma_bf16(acc[mt][2*j],   ah[mt], b4[0], b4[1]);
                    mma_bf16(acc[mt][2*j+1], ah[mt], b4[2], b4[3]);
                }
            }
        }
        __syncthreads();
    }

    const int trow = lane >> 2;
    const int tcol = (lane & 3) * 2;
#pragma unroll
    for (int mt = 0; mt < 2; mt++) {
        const int r0 = m0 + warp_m * 32 + mt * 16 + trow;
#pragma unroll
        for (int nt = 0; nt < 8; nt++) {
            const int col = n0 + warp_n * 64 + nt * 8 + tcol;
            float2 b2 = *(const float2*)(bias + col);
            float x0 = (acc[mt][nt][0] + b2.x) * oscale;
            float x1 = (acc[mt][nt][1] + b2.y) * oscale;
            float x2 = (acc[mt][nt][2] + b2.x) * oscale;
            float x3 = (acc[mt][nt][3] + b2.y) * oscale;
            if (Cf) {
                *(float2*)(Cf + (size_t)r0 * Dc + col)       = make_float2(x0, x1);
                *(float2*)(Cf + (size_t)(r0 + 8) * Dc + col) = make_float2(x2, x3);
            } else {
                uint32_t h0, l0, h1, l1;
                split2(x0, x1, h0, l0);
                split2(x2, x3, h1, l1);
                *(uint32_t*)(Ch + (size_t)r0 * Dc + col)       = h0;
                *(uint32_t*)(Cl + (size_t)r0 * Dc + col)       = l0;
                *(uint32_t*)(Ch + (size_t)(r0 + 8) * Dc + col) = h1;
                *(uint32_t*)(Cl + (size_t)(r0 + 8) * Dc + col) = l1;
            }
        }
    }
}

// ---------------------------------------------------------------------------
// Double-buffered tensor-core flash attention.
// BQ=128 (8 warps x 16 rows), BKV=64, DK=64. Dynamic smem: 2 x 32KB.
// Output: split bf16 directly into g_Xh / g_Xl.
// ---------------------------------------------------------------------------
__global__ void __launch_bounds__(256) attn_tc_kernel()
{
    extern __shared__ __align__(128) char smem[];
    const uint32_t sb = smem_u32(smem);

    const int tid  = threadIdx.x;
    const int lane = tid & 31;
    const int wid  = tid >> 5;
    const int qt   = blockIdx.x;
    const int bh   = blockIdx.y;
    const int b    = bh >> 4, h = bh & 15;
    const int q0   = qt * 128;
    const int grp  = lane >> 2;
    const int lc2  = (lane & 3) * 2;

    // Q fragments (hi/lo), resident.
    uint32_t qfh[4][4], qfl[4][4];
    {
        const size_t rbase = (size_t)(b * Sc + q0 + wid * 16 + grp) * Dc + h * DKc;
#pragma unroll
        for (int ks = 0; ks < 4; ++ks)
#pragma unroll
            for (int r2 = 0; r2 < 2; ++r2)
#pragma unroll
                for (int kh = 0; kh < 2; ++kh) {
                    size_t off = rbase + (size_t)r2 * 8 * Dc + ks * 16 + kh * 8 + lc2;
                    qfh[ks][r2 + 2*kh] = *(const uint32_t*)(g_Qh + off);
                    qfl[ks][r2 + 2*kh] = *(const uint32_t*)(g_Ql + off);
                }
    }

    const int rowsm = ((lane >> 4) << 3) + (lane & 7);
    const int chx   = ((lane >> 3) & 1);
    const int l7    = lane & 7;
    const uint32_t baseK = sb + rowsm * 128;
    const uint32_t baseV = sb + 16384 + rowsm * 128;

    float m[2] = {-INFINITY, -INFINITY};
    float l[2] = {0.f, 0.f};
    float O[4][2][4];
#pragma unroll
    for (int jv = 0; jv < 4; jv++)
#pragma unroll
        for (int t = 0; t < 2; t++)
#pragma unroll
            for (int e = 0; e < 4; e++) O[jv][t][e] = 0.f;

    const __nv_bfloat16* Khg  = g_Kh  + (size_t)b * Sc * Dc + h * DKc;
    const __nv_bfloat16* Klg  = g_Kl  + (size_t)b * Sc * Dc + h * DKc;
    const __nv_bfloat16* VThg = g_VTh + (size_t)bh * DKc * Sc;
    const __nv_bfloat16* VTlg = g_VTl + (size_t)bh * DKc * Sc;

    auto stage = [&](int kt, int buf) {
        const int k0 = kt * 64;
        const uint32_t bo = sb + (buf << 15);
#pragma unroll
        for (int i = 0; i < 8; ++i) {
            const int t   = i >> 1;
            const int c   = tid + (i & 1) * 256;
            const int row = c >> 3;
            const int ch  = c & 7;
            const uint32_t so = (uint32_t)(t * 8192 + row * 128 + ((ch ^ (row & 7)) << 4));
            const __nv_bfloat16* src;
            size_t gi;
            if (t < 2) {
                src = (t == 0) ? Khg : Klg;
                gi  = (size_t)(k0 + row) * Dc + ch * 8;
            } else {
                src = (t == 2) ? VThg : VTlg;
                gi  = (size_t)row * Sc + k0 + ch * 8;
            }
            cp16(bo + so, src + gi);
        }
        CP_COMMIT();
    };

    stage(0, 0);

    for (int kt = 0; kt < Sc / 64; ++kt) {
        const bool has_next = (kt + 1) < (Sc / 64);
        if (has_next) stage(kt + 1, (kt + 1) & 1);
        if (has_next) CP_WAIT(1); else CP_WAIT(0);
        __syncthreads();
        const uint32_t bo = (uint32_t)((kt & 1) << 15);

        // S = Q.K^T (3 split terms)
        float S[4][2][4];
#pragma unroll
        for (int j = 0; j < 4; j++)
#pragma unroll
            for (int t = 0; t < 2; t++)
#pragma unroll
                for (int e = 0; e < 4; e++) S[j][t][e] = 0.f;

#pragma unroll
        for (int ks = 0; ks < 4; ++ks)
#pragma unroll
            for (int j = 0; j < 4; ++j) {
                uint32_t b4[4];
                uint32_t a0 = baseK + bo + j * 2048 + (((ks * 2 + chx) ^ l7) << 4);
                ldsm_x4(b4[0], b4[1], b4[2], b4[3], a0);
                mma_bf16(S[j][0], qfh[ks], b4[0], b4[1]);
                mma_bf16(S[j][1], qfh[ks], b4[2], b4[3]);
                mma_bf16(S[j][0], qfl[ks], b4[0], b4[1]);
                mma_bf16(S[j][1], qfl[ks], b4[2], b4[3]);
                ldsm_x4(b4[0], b4[1], b4[2], b4[3], a0 + 8192);
                mma_bf16(S[j][0], qfh[ks], b4[0], b4[1]);
                mma_bf16(S[j][1], qfh[ks], b4[2], b4[3]);
            }

        // Online softmax
#pragma unroll
        for (int r2 = 0; r2 < 2; ++r2) {
            float mx = -INFINITY;
#pragma unroll
            for (int j = 0; j < 4; j++)
#pragma unroll
                for (int t = 0; t < 2; t++)
                    mx = fmaxf(mx, fmaxf(S[j][t][2*r2], S[j][t][2*r2+1]));
            mx = fmaxf(mx, __shfl_xor_sync(0xffffffffu, mx, 1));
            mx = fmaxf(mx, __shfl_xor_sync(0xffffffffu, mx, 2));
            float mn   = fmaxf(m[r2], mx);
            float corr = __expf(m[r2] - mn);
            m[r2] = mn;
            float sum = 0.f;
#pragma unroll
            for (int j = 0; j < 4; j++)
#pragma unroll
                for (int t = 0; t < 2; t++) {
                    float p0 = __expf(S[j][t][2*r2]   - mn);
                    float p1 = __expf(S[j][t][2*r2+1] - mn);
                    S[j][t][2*r2]   = p0;
                    S[j][t][2*r2+1] = p1;
                    sum += p0 + p1;
                }
            sum += __shfl_xor_sync(0xffffffffu, sum, 1);
            sum += __shfl_xor_sync(0xffffffffu, sum, 2);
            l[r2] = l[r2] * corr + sum;
#pragma unroll
            for (int jv = 0; jv < 4; jv++)
#pragma unroll
                for (int t = 0; t < 2; t++) {
                    O[jv][t][2*r2]   *= corr;
                    O[jv][t][2*r2+1] *= corr;
                }
        }

        // O += P.V (3 split terms)
#pragma unroll
        for (int ksv = 0; ksv < 4; ++ksv) {
            uint32_t ph[4], pl[4];
#pragma unroll
            for (int t = 0; t < 2; t++)
#pragma unroll
                for (int r2 = 0; r2 < 2; r2++) {
                    split2(S[ksv][t][2*r2], S[ksv][t][2*r2+1],
                           ph[r2 + 2*t], pl[r2 + 2*t]);
                }
#pragma unroll
            for (int jv = 0; jv < 4; ++jv) {
                uint32_t b4[4];
                uint32_t a0 = baseV + bo + jv * 2048 + (((ksv * 2 + chx) ^ l7) << 4);
                ldsm_x4(b4[0], b4[1], b4[2], b4[3], a0);
                mma_bf16(O[jv][0], ph, b4[0], b4[1]);
                mma_bf16(O[jv][1], ph, b4[2], b4[3]);
                mma_bf16(O[jv][0], pl, b4[0], b4[1]);
                mma_bf16(O[jv][1], pl, b4[2], b4[3]);
                ldsm_x4(b4[0], b4[1], b4[2], b4[3], a0 + 8192);
                mma_bf16(O[jv][0], ph, b4[0], b4[1]);
                mma_bf16(O[jv][1], ph, b4[2], b4[3]);
            }
        }
        __syncthreads();
    }

    // Epilogue: normalize, split to bf16 hi/lo, write g_Xh/g_Xl.
    const float inv0 = 1.f / l[0];
    const float inv1 = 1.f / l[1];
    __nv_bfloat16* OgH = g_Xh + (size_t)b * Sc * Dc + h * DKc;
    __nv_bfloat16* OgL = g_Xl + (size_t)b * Sc * Dc + h * DKc;
    const int r0 = q0 + wid * 16 + grp;
#pragma unroll
    for (int jv = 0; jv < 4; ++jv)
#pragma unroll
        for (int t = 0; t < 2; ++t) {
            const int col = jv * 16 + t * 8 + lc2;
            uint32_t h0, l0, h1, l1;
            split2(O[jv][t][0] * inv0, O[jv][t][1] * inv0, h0, l0);
            split2(O[jv][t][2] * inv1, O[jv][t][3] * inv1, h1, l1);
            *(uint32_t*)(OgH + (size_t)r0 * Dc + col)       = h0;
            *(uint32_t*)(OgL + (size_t)r0 * Dc + col)       = l0;
            *(uint32_t*)(OgH + (size_t)(r0 + 8) * Dc + col) = h1;
            *(uint32_t*)(OgL + (size_t)(r0 + 8) * Dc + col) = l1;
        }
}

// ---------------------------------------------------------------------------
// Launch
// ---------------------------------------------------------------------------
extern "C" void kernel_launch(void* const* d_in, const int* in_sizes, int n_in,
                              void* d_out, int out_size)
{
    const float* q  = (const float*)d_in[0];
    const float* k  = (const float*)d_in[1];
    const float* v  = (const float*)d_in[2];
    const float* wq = (const float*)d_in[3];
    const float* bq = (const float*)d_in[4];
    const float* wk = (const float*)d_in[5];
    const float* bk = (const float*)d_in[6];
    const float* wv = (const float*)d_in[7];
    const float* bv = (const float*)d_in[8];
    const float* wo = (const float*)d_in[9];
    const float* bo = (const float*)d_in[10];
    float* out = (float*)d_out;

    float *pV;
    __nv_bfloat16 *pXh, *pXl, *pWh, *pWl, *pQh, *pQl, *pKh, *pKl, *pVTh, *pVTl;
    cudaGetSymbolAddress((void**)&pV, g_V);
    cudaGetSymbolAddress((void**)&pXh, g_Xh);
    cudaGetSymbolAddress((void**)&pXl, g_Xl);
    cudaGetSymbolAddress((void**)&pWh, g_Wh);
    cudaGetSymbolAddress((void**)&pWl, g_Wl);
    cudaGetSymbolAddress((void**)&pQh, g_Qh);
    cudaGetSymbolAddress((void**)&pQl, g_Ql);
    cudaGetSymbolAddress((void**)&pKh, g_Kh);
    cudaGetSymbolAddress((void**)&pKl, g_Kl);
    cudaGetSymbolAddress((void**)&pVTh, g_VTh);
    cudaGetSymbolAddress((void**)&pVTl, g_VTl);

    cudaFuncSetAttribute(gemm_tc_kernel,
                         cudaFuncAttributeMaxDynamicSharedMemorySize, 65536);
    cudaFuncSetAttribute(attn_tc_kernel,
                         cudaFuncAttributeMaxDynamicSharedMemorySize, 65536);

    const int n4 = MROWS * Dc / 4;
    dim3 cwgrid(Dc / 32, Dc / 32), cwblk(32, 8);
    dim3 ggrid(Dc / 128, MROWS / 128);

    // Q projection -> split bf16 (pre-scaled by 1/sqrt(DK))
    conv_wT_kernel<<<cwgrid, cwblk>>>(wq, pWh, pWl);
    conv_act_kernel<<<n4 / 256, 256>>>(q, pXh, pXl, n4, 1.f);
    gemm_tc_kernel<<<ggrid, 256, 65536>>>(pXh, pXl, pWh, pWl, bq,
                                          nullptr, pQh, pQl, 0.125f);
    // K projection -> split bf16
    conv_wT_kernel<<<cwgrid, cwblk>>>(wk, pWh, pWl);
    conv_act_kernel<<<n4 / 256, 256>>>(k, pXh, pXl, n4, 1.f);
    gemm_tc_kernel<<<ggrid, 256, 65536>>>(pXh, pXl, pWh, pWl, bk,
                                          nullptr, pKh, pKl, 1.f);
    // V projection -> fp32, then transpose-split
    conv_wT_kernel<<<cwgrid, cwblk>>>(wv, pWh, pWl);
    conv_act_kernel<<<n4 / 256, 256>>>(v, pXh, pXl, n4, 1.f);
    gemm_tc_kernel<<<ggrid, 256, 65536>>>(pXh, pXl, pWh, pWl, bv,
                                          pV, nullptr, nullptr, 1.f);
    dim3 vtgrid(Sc / 32, DKc / 32, Bc * Hc);
    conv_vT_kernel<<<vtgrid, cwblk>>>(pV, pVTh, pVTl);

    // Attention -> writes split g_Xh/g_Xl directly
    dim3 agrid(Sc / 128, Bc * Hc);
    attn_tc_kernel<<<agrid, 256, 65536>>>();

    // Output projection (reads g_Xh/g_Xl)
    conv_wT_kernel<<<cwgrid, cwblk>>>(wo, pWh, pWl);
    gemm_tc_kernel<<<ggrid, 256, 65536>>>(pXh, pXl, pWh, pWl, bo,
                                          out, nullptr, nullptr, 1.f);
}

// round 6
// speedup vs baseline: 3.4196x; 1.0873x over previous
#include <cuda_runtime.h>
#include <cuda_bf16.h>
#include <math.h>
#include <stdint.h>

// Problem constants
#define Bc 4
#define Sc 2048
#define Dc 1024
#define Hc 16
#define DKc 64
#define MROWS (Bc * Sc)   // 8192
#define MD (MROWS * Dc)
#define DD (Dc * Dc)

// Split bf16 scratch
__device__ __nv_bfloat16 g_X3h[3 * MD], g_X3l[3 * MD];   // activations (q,k,v) / attn out in slot 0
__device__ __nv_bfloat16 g_W3h[3 * DD], g_W3l[3 * DD];   // transposed weights
__device__ __nv_bfloat16 g_Qh[MD], g_Ql[MD];
__device__ __nv_bfloat16 g_Kh[MD], g_Kl[MD];
__device__ __nv_bfloat16 g_VTh[MD], g_VTl[MD];           // [bh][dk][s]

// ---------------------------------------------------------------------------
// Helpers
// ---------------------------------------------------------------------------
__device__ __forceinline__ uint32_t smem_u32(const void* p) {
    uint32_t a;
    asm("{ .reg .u64 t; cvta.to.shared.u64 t, %1; cvt.u32.u64 %0, t; }"
        : "=r"(a) : "l"(p));
    return a;
}

__device__ __forceinline__ void ldsm_x4(uint32_t& r0, uint32_t& r1,
                                        uint32_t& r2, uint32_t& r3,
                                        uint32_t addr) {
    asm volatile("ldmatrix.sync.aligned.m8n8.x4.shared.b16 {%0,%1,%2,%3}, [%4];"
                 : "=r"(r0), "=r"(r1), "=r"(r2), "=r"(r3) : "r"(addr));
}

__device__ __forceinline__ void mma_bf16(float* c, const uint32_t* a,
                                         uint32_t b0, uint32_t b1) {
    asm volatile(
        "mma.sync.aligned.m16n8k16.row.col.f32.bf16.bf16.f32 "
        "{%0,%1,%2,%3}, {%4,%5,%6,%7}, {%8,%9}, {%0,%1,%2,%3};"
        : "+f"(c[0]), "+f"(c[1]), "+f"(c[2]), "+f"(c[3])
        : "r"(a[0]), "r"(a[1]), "r"(a[2]), "r"(a[3]), "r"(b0), "r"(b1));
}

__device__ __forceinline__ uint32_t pack2(float a, float b) {
    __nv_bfloat162 h2 = __floats2bfloat162_rn(a, b);   // x=a (low), y=b (high)
    return *(uint32_t*)&h2;
}

// fast split: hi = rn(a),rn(b) packed; lo = residuals (hi reconstructed by shift, exact)
__device__ __forceinline__ void split2(float a, float b,
                                       uint32_t& hi, uint32_t& lo) {
    uint32_t h = pack2(a, b);
    float fa = __uint_as_float(h << 16);
    float fb = __uint_as_float(h & 0xffff0000u);
    hi = h;
    lo = pack2(a - fa, b - fb);
}

__device__ __forceinline__ void cp16(uint32_t dst, const void* src) {
    asm volatile("cp.async.cg.shared.global [%0], [%1], 16;"
                 :: "r"(dst), "l"(src));
}
#define CP_COMMIT() asm volatile("cp.async.commit_group;" ::: "memory")
#define CP_WAIT(n)  asm volatile("cp.async.wait_group %0;" :: "n"(n) : "memory")

// ---------------------------------------------------------------------------
// Batched fp32 -> split bf16 (z selects source)
// ---------------------------------------------------------------------------
__global__ void __launch_bounds__(256) conv_act3_kernel(
    const float* __restrict__ x0, const float* __restrict__ x1,
    const float* __restrict__ x2,
    __nv_bfloat16* __restrict__ Hb, __nv_bfloat16* __restrict__ Lb, int n4)
{
    int i = blockIdx.x * blockDim.x + threadIdx.x;
    if (i >= n4) return;
    const int z = blockIdx.z;
    const float* X = (z == 0) ? x0 : (z == 1) ? x1 : x2;
    __nv_bfloat16* H = Hb + (size_t)z * MD;
    __nv_bfloat16* L = Lb + (size_t)z * MD;
    float4 v = ((const float4*)X)[i];
    uint32_t hp[2], lp[2];
    split2(v.x, v.y, hp[0], lp[0]);
    split2(v.z, v.w, hp[1], lp[1]);
    ((uint2*)H)[i] = make_uint2(hp[0], hp[1]);
    ((uint2*)L)[i] = make_uint2(lp[0], lp[1]);
}

// ---------------------------------------------------------------------------
// Batched weight [K,N] -> transposed split [N,K] hi/lo (z selects source)
// ---------------------------------------------------------------------------
__global__ void __launch_bounds__(256) conv_wT3_kernel(
    const float* __restrict__ w0, const float* __restrict__ w1,
    const float* __restrict__ w2,
    __nv_bfloat16* __restrict__ Thb, __nv_bfloat16* __restrict__ Tlb)
{
    __shared__ float t[32][33];
    const int z = blockIdx.z;
    const float* W = (z == 0) ? w0 : (z == 1) ? w1 : w2;
    __nv_bfloat16* Th = Thb + (size_t)z * DD;
    __nv_bfloat16* Tl = Tlb + (size_t)z * DD;
    int n0 = blockIdx.x * 32;
    int k0 = blockIdx.y * 32;
    int tx = threadIdx.x, ty = threadIdx.y;
#pragma unroll
    for (int i = 0; i < 4; i++)
        t[ty + 8*i][tx] = W[(size_t)(k0 + ty + 8*i) * Dc + n0 + tx];
    __syncthreads();
#pragma unroll
    for (int i = 0; i < 4; i++) {
        float v = t[tx][ty + 8*i];
        uint32_t h, l;
        split2(v, 0.f, h, l);
        size_t idx = (size_t)(n0 + ty + 8*i) * Dc + k0 + tx;
        Th[idx] = __ushort_as_bfloat16((unsigned short)(h & 0xffff));
        Tl[idx] = __ushort_as_bfloat16((unsigned short)(l & 0xffff));
    }
}

// ---------------------------------------------------------------------------
// 3-stage ring mma.sync split-3 GEMM.
// modes: batched z=0 -> split out (Q, oscale .125); z=1 -> split out (K);
//        z=2 -> transposed split out (VT). non-batched -> fp32 out (Cf).
// Tile 128x128, BK=32, 8 warps. Dynamic smem: 3 x 32KB (mode2 reuses for transpose).
// ---------------------------------------------------------------------------
#define GEMM_SMEM (3 * 32768)

__global__ void __launch_bounds__(256) gemm_tc_kernel(
    const __nv_bfloat16* __restrict__ Abh, const __nv_bfloat16* __restrict__ Abl,
    const __nv_bfloat16* __restrict__ Bbh, const __nv_bfloat16* __restrict__ Bbl,
    const float* __restrict__ bias0, const float* __restrict__ bias1,
    const float* __restrict__ bias2,
    float* __restrict__ Cf,
    __nv_bfloat16* __restrict__ Qoh, __nv_bfloat16* __restrict__ Qol,
    __nv_bfloat16* __restrict__ Koh, __nv_bfloat16* __restrict__ Kol,
    __nv_bfloat16* __restrict__ Voh, __nv_bfloat16* __restrict__ Vol,
    int batched)
{
    extern __shared__ __align__(128) char smem[];
    const uint32_t sb = smem_u32(smem);

    const int z = batched ? blockIdx.z : 0;
    const __nv_bfloat16* Ah = Abh + (size_t)z * MD;
    const __nv_bfloat16* Al = Abl + (size_t)z * MD;
    const __nv_bfloat16* Bh = Bbh + (size_t)z * DD;
    const __nv_bfloat16* Bl = Bbl + (size_t)z * DD;
    const float* bias = (z == 0) ? bias0 : (z == 1) ? bias1 : bias2;
    const int mode = batched ? ((z == 2) ? 2 : 1) : 0;
    const float oscale = (batched && z == 0) ? 0.125f : 1.f;
    __nv_bfloat16* Ch = (z == 0) ? Qoh : Koh;
    __nv_bfloat16* Cl = (z == 0) ? Qol : Kol;

    const int tid    = threadIdx.x;
    const int lane   = tid & 31;
    const int wid    = tid >> 5;
    const int warp_m = wid >> 1;
    const int warp_n = wid & 1;
    const int m0     = blockIdx.y * 128;
    const int n0     = blockIdx.x * 128;

    float acc[2][8][4];
#pragma unroll
    for (int mt = 0; mt < 2; mt++)
#pragma unroll
        for (int nt = 0; nt < 8; nt++)
#pragma unroll
            for (int e = 0; e < 4; e++) acc[mt][nt][e] = 0.f;

    uint32_t aAddr[2][2], bAddr[4][2];
#pragma unroll
    for (int mt = 0; mt < 2; mt++)
#pragma unroll
        for (int ks = 0; ks < 2; ks++) {
            int row = warp_m * 32 + mt * 16 + (lane & 15);
            int ch  = ks * 2 + (lane >> 4);
            aAddr[mt][ks] = sb + row * 64 + ((ch ^ ((row >> 1) & 3)) << 4);
        }
#pragma unroll
    for (int j = 0; j < 4; j++)
#pragma unroll
        for (int ks = 0; ks < 2; ks++) {
            int row = warp_n * 64 + j * 16 + ((lane >> 4) << 3) + (lane & 7);
            int ch  = ks * 2 + ((lane >> 3) & 1);
            bAddr[j][ks] = sb + 16384 + row * 64 + ((ch ^ ((row >> 1) & 3)) << 4);
        }

    const __nv_bfloat16* gsrc[4] = {Ah, Al, Bh, Bl};
    const int rowbase[4] = {m0, m0, n0, n0};

    auto stage = [&](int kt, int buf) {
        const int k0 = kt * 32;
        const uint32_t bo = sb + (uint32_t)(buf << 15);
#pragma unroll
        for (int i = 0; i < 8; ++i) {
            const int t   = i >> 1;
            const int c   = tid + (i & 1) * 256;
            const int row = c >> 2;
            const int ch  = c & 3;
            uint32_t so = (uint32_t)(t * 8192 + row * 64 +
                                     ((ch ^ ((row >> 1) & 3)) << 4));
            size_t gi = (((size_t)(rowbase[t] + row)) << 10) + k0 + ch * 8;
            cp16(bo + so, gsrc[t] + gi);
        }
        CP_COMMIT();
    };

    stage(0, 0);
    stage(1, 1);

    const int NK = Dc / 32;   // 32
    int buf = 0;
    for (int kt = 0; kt < NK; ++kt) {
        if (kt == NK - 1) { CP_WAIT(0); } else { CP_WAIT(1); }
        __syncthreads();
        if (kt + 2 < NK) {
            int nb = buf + 2; if (nb >= 3) nb -= 3;
            stage(kt + 2, nb);
        }
        const uint32_t bo = (uint32_t)(buf << 15);
#pragma unroll
        for (int ks = 0; ks < 2; ++ks) {
            uint32_t ah[2][4], al[2][4];
#pragma unroll
            for (int mt = 0; mt < 2; mt++) {
                ldsm_x4(ah[mt][0], ah[mt][1], ah[mt][2], ah[mt][3], aAddr[mt][ks] + bo);
                ldsm_x4(al[mt][0], al[mt][1], al[mt][2], al[mt][3], aAddr[mt][ks] + bo + 8192);
            }
#pragma unroll
            for (int j = 0; j < 4; ++j) {
                uint32_t b4[4];
                ldsm_x4(b4[0], b4[1], b4[2], b4[3], bAddr[j][ks] + bo);
#pragma unroll
                for (int mt = 0; mt < 2; mt++) {
                    mma_bf16(acc[mt][2*j],   ah[mt], b4[0], b4[1]);
                    mma_bf16(acc[mt][2*j+1], ah[mt], b4[2], b4[3]);
                    mma_bf16(acc[mt][2*j],   al[mt], b4[0], b4[1]);
                    mma_bf16(acc[mt][2*j+1], al[mt], b4[2], b4[3]);
                }
                ldsm_x4(b4[0], b4[1], b4[2], b4[3], bAddr[j][ks] + bo + 8192);
#pragma unroll
                for (int mt = 0; mt < 2; mt++) {
                    mma_bf16(acc[mt][2*j],   ah[mt], b4[0], b4[1]);
                    mma_bf16(acc[mt][2*j+1], ah[mt], b4[2], b4[3]);
                }
            }
        }
        if (++buf == 3) buf = 0;
    }

    const int trow = lane >> 2;
    const int tcol = (lane & 3) * 2;

    if (mode == 2) {
        // Transposed split epilogue: acc -> smem (raw), read transposed, +bias, split.
        __syncthreads();   // all warps done reading ring buffers
        float* st = (float*)smem;   // tile [128][132]
#pragma unroll
        for (int mt = 0; mt < 2; mt++) {
            const int r = warp_m * 32 + mt * 16 + trow;
#pragma unroll
            for (int nt = 0; nt < 8; nt++) {
                const int c = warp_n * 64 + nt * 8 + tcol;
                st[(size_t)r * 132 + c]           = acc[mt][nt][0];
                st[(size_t)r * 132 + c + 1]       = acc[mt][nt][1];
                st[(size_t)(r + 8) * 132 + c]     = acc[mt][nt][2];
                st[(size_t)(r + 8) * 132 + c + 1] = acc[mt][nt][3];
            }
        }
        __syncthreads();
        // thread -> (tile col c, s-half). c = head-local dk over 2 heads.
        const int c  = tid >> 1;            // 0..127
        const int sh = (tid & 1) * 64;      // s-half within tile
        const int head = (n0 >> 6) + (c >> 6);
        const int dk   = c & 63;
        const int bidx = m0 >> 11;          // batch (m0 / 2048)
        const int s0   = (m0 & 2047) + sh;
        const float bc = bias[n0 + c];
        size_t vbase = ((size_t)(bidx * Hc + head) * DKc + dk) * Sc + s0;
#pragma unroll
        for (int blk = 0; blk < 8; ++blk) {
            uint32_t hi[4], lo[4];
#pragma unroll
            for (int p = 0; p < 4; ++p) {
                float v0 = st[(size_t)(sh + blk * 8 + 2*p)     * 132 + c] + bc;
                float v1 = st[(size_t)(sh + blk * 8 + 2*p + 1) * 132 + c] + bc;
                split2(v0, v1, hi[p], lo[p]);
            }
            *(uint4*)(Voh + vbase + blk * 8) = make_uint4(hi[0], hi[1], hi[2], hi[3]);
            *(uint4*)(Vol + vbase + blk * 8) = make_uint4(lo[0], lo[1], lo[2], lo[3]);
        }
        return;
    }

#pragma unroll
    for (int mt = 0; mt < 2; mt++) {
        const int r0 = m0 + warp_m * 32 + mt * 16 + trow;
#pragma unroll
        for (int nt = 0; nt < 8; nt++) {
            const int col = n0 + warp_n * 64 + nt * 8 + tcol;
            float2 b2 = *(const float2*)(bias + col);
            float x0 = (acc[mt][nt][0] + b2.x) * oscale;
            float x1 = (acc[mt][nt][1] + b2.y) * oscale;
            float x2 = (acc[mt][nt][2] + b2.x) * oscale;
            float x3 = (acc[mt][nt][3] + b2.y) * oscale;
            if (mode == 0) {
                *(float2*)(Cf + (size_t)r0 * Dc + col)       = make_float2(x0, x1);
                *(float2*)(Cf + (size_t)(r0 + 8) * Dc + col) = make_float2(x2, x3);
            } else {
                uint32_t h0, l0, h1, l1;
                split2(x0, x1, h0, l0);
                split2(x2, x3, h1, l1);
                *(uint32_t*)(Ch + (size_t)r0 * Dc + col)       = h0;
                *(uint32_t*)(Cl + (size_t)r0 * Dc + col)       = l0;
                *(uint32_t*)(Ch + (size_t)(r0 + 8) * Dc + col) = h1;
                *(uint32_t*)(Cl + (size_t)(r0 + 8) * Dc + col) = l1;
            }
        }
    }
}

// ---------------------------------------------------------------------------
// 3-stage ring tensor-core flash attention.
// BQ=128 (8 warps x 16 rows), BKV=64, DK=64. Smem 3 x 32KB; ONE barrier/iter.
// Output: split bf16 into g_X3h/g_X3l slot 0.
// ---------------------------------------------------------------------------
#define ATTN_SMEM (3 * 32768)

__global__ void __launch_bounds__(256) attn_tc_kernel()
{
    extern __shared__ __align__(128) char smem[];
    const uint32_t sb = smem_u32(smem);

    const int tid  = threadIdx.x;
    const int lane = tid & 31;
    const int wid  = tid >> 5;
    const int qt   = blockIdx.x;
    const int bh   = blockIdx.y;
    const int b    = bh >> 4, h = bh & 15;
    const int q0   = qt * 128;
    const int grp  = lane >> 2;
    const int lc2  = (lane & 3) * 2;

    // Q fragments (hi/lo), resident.
    uint32_t qfh[4][4], qfl[4][4];
    {
        const size_t rbase = (size_t)(b * Sc + q0 + wid * 16 + grp) * Dc + h * DKc;
#pragma unroll
        for (int ks = 0; ks < 4; ++ks)
#pragma unroll
            for (int r2 = 0; r2 < 2; ++r2)
#pragma unroll
                for (int kh = 0; kh < 2; ++kh) {
                    size_t off = rbase + (size_t)r2 * 8 * Dc + ks * 16 + kh * 8 + lc2;
                    qfh[ks][r2 + 2*kh] = *(const uint32_t*)(g_Qh + off);
                    qfl[ks][r2 + 2*kh] = *(const uint32_t*)(g_Ql + off);
                }
    }

    const int rowsm = ((lane >> 4) << 3) + (lane & 7);
    const int chx   = ((lane >> 3) & 1);
    const int l7    = lane & 7;
    const uint32_t baseK = sb + rowsm * 128;
    const uint32_t baseV = sb + 16384 + rowsm * 128;

    float m[2] = {-INFINITY, -INFINITY};
    float l[2] = {0.f, 0.f};
    float O[4][2][4];
#pragma unroll
    for (int jv = 0; jv < 4; jv++)
#pragma unroll
        for (int t = 0; t < 2; t++)
#pragma unroll
            for (int e = 0; e < 4; e++) O[jv][t][e] = 0.f;

    const __nv_bfloat16* Khg  = g_Kh  + (size_t)b * Sc * Dc + h * DKc;
    const __nv_bfloat16* Klg  = g_Kl  + (size_t)b * Sc * Dc + h * DKc;
    const __nv_bfloat16* VThg = g_VTh + (size_t)bh * DKc * Sc;
    const __nv_bfloat16* VTlg = g_VTl + (size_t)bh * DKc * Sc;

    auto stage = [&](int kt, int buf) {
        const int k0 = kt * 64;
        const uint32_t bo = sb + (uint32_t)(buf << 15);
#pragma unroll
        for (int i = 0; i < 8; ++i) {
            const int t   = i >> 1;
            const int c   = tid + (i & 1) * 256;
            const int row = c >> 3;
            const int ch  = c & 7;
            const uint32_t so = (uint32_t)(t * 8192 + row * 128 + ((ch ^ (row & 7)) << 4));
            const __nv_bfloat16* src;
            size_t gi;
            if (t < 2) {
                src = (t == 0) ? Khg : Klg;
                gi  = (size_t)(k0 + row) * Dc + ch * 8;
            } else {
                src = (t == 2) ? VThg : VTlg;
                gi  = (size_t)row * Sc + k0 + ch * 8;
            }
            cp16(bo + so, src + gi);
        }
        CP_COMMIT();
    };

    stage(0, 0);
    stage(1, 1);

    const int NT = Sc / 64;   // 32
    int buf = 0;
    for (int kt = 0; kt < NT; ++kt) {
        if (kt == NT - 1) { CP_WAIT(0); } else { CP_WAIT(1); }
        __syncthreads();
        if (kt + 2 < NT) {
            int nb = buf + 2; if (nb >= 3) nb -= 3;
            stage(kt + 2, nb);
        }
        const uint32_t bo = (uint32_t)(buf << 15);

        // S = Q.K^T (3 split terms)
        float S[4][2][4];
#pragma unroll
        for (int j = 0; j < 4; j++)
#pragma unroll
            for (int t = 0; t < 2; t++)
#pragma unroll
                for (int e = 0; e < 4; e++) S[j][t][e] = 0.f;

#pragma unroll
        for (int ks = 0; ks < 4; ++ks)
#pragma unroll
            for (int j = 0; j < 4; ++j) {
                uint32_t b4[4];
                uint32_t a0 = baseK + bo + j * 2048 + (((ks * 2 + chx) ^ l7) << 4);
                ldsm_x4(b4[0], b4[1], b4[2], b4[3], a0);
                mma_bf16(S[j][0], qfh[ks], b4[0], b4[1]);
                mma_bf16(S[j][1], qfh[ks], b4[2], b4[3]);
                mma_bf16(S[j][0], qfl[ks], b4[0], b4[1]);
                mma_bf16(S[j][1], qfl[ks], b4[2], b4[3]);
                ldsm_x4(b4[0], b4[1], b4[2], b4[3], a0 + 8192);
                mma_bf16(S[j][0], qfh[ks], b4[0], b4[1]);
                mma_bf16(S[j][1], qfh[ks], b4[2], b4[3]);
            }

        // Online softmax with corr-skip
#pragma unroll
        for (int r2 = 0; r2 < 2; ++r2) {
            float mx = -INFINITY;
#pragma unroll
            for (int j = 0; j < 4; j++)
#pragma unroll
                for (int t = 0; t < 2; t++)
                    mx = fmaxf(mx, fmaxf(S[j][t][2*r2], S[j][t][2*r2+1]));
            mx = fmaxf(mx, __shfl_xor_sync(0xffffffffu, mx, 1));
            mx = fmaxf(mx, __shfl_xor_sync(0xffffffffu, mx, 2));
            const float mold = m[r2];
            const float mn   = fmaxf(mold, mx);
            m[r2] = mn;
            float sum = 0.f;
#pragma unroll
            for (int j = 0; j < 4; j++)
#pragma unroll
                for (int t = 0; t < 2; t++) {
                    float p0 = __expf(S[j][t][2*r2]   - mn);
                    float p1 = __expf(S[j][t][2*r2+1] - mn);
                    S[j][t][2*r2]   = p0;
                    S[j][t][2*r2+1] = p1;
                    sum += p0 + p1;
                }
            sum += __shfl_xor_sync(0xffffffffu, sum, 1);
            sum += __shfl_xor_sync(0xffffffffu, sum, 2);
            if (mn > mold) {
                float corr = __expf(mold - mn);
                l[r2] = l[r2] * corr + sum;
#pragma unroll
                for (int jv = 0; jv < 4; jv++)
#pragma unroll
                    for (int t = 0; t < 2; t++) {
                        O[jv][t][2*r2]   *= corr;
                        O[jv][t][2*r2+1] *= corr;
                    }
            } else {
                l[r2] += sum;
            }
        }

        // O += P.V (3 split terms)
#pragma unroll
        for (int ksv = 0; ksv < 4; ++ksv) {
            uint32_t ph[4], pl[4];
#pragma unroll
            for (int t = 0; t < 2; t++)
#pragma unroll
                for (int r2 = 0; r2 < 2; r2++) {
                    split2(S[ksv][t][2*r2], S[ksv][t][2*r2+1],
                           ph[r2 + 2*t], pl[r2 + 2*t]);
                }
#pragma unroll
            for (int jv = 0; jv < 4; ++jv) {
                uint32_t b4[4];
                uint32_t a0 = baseV + bo + jv * 2048 + (((ksv * 2 + chx) ^ l7) << 4);
                ldsm_x4(b4[0], b4[1], b4[2], b4[3], a0);
                mma_bf16(O[jv][0], ph, b4[0], b4[1]);
                mma_bf16(O[jv][1], ph, b4[2], b4[3]);
                mma_bf16(O[jv][0], pl, b4[0], b4[1]);
                mma_bf16(O[jv][1], pl, b4[2], b4[3]);
                ldsm_x4(b4[0], b4[1], b4[2], b4[3], a0 + 8192);
                mma_bf16(O[jv][0], ph, b4[0], b4[1]);
                mma_bf16(O[jv][1], ph, b4[2], b4[3]);
            }
        }
        if (++buf == 3) buf = 0;
    }

    // Epilogue: normalize, split, write attn output into X slot 0.
    const float inv0 = 1.f / l[0];
    const float inv1 = 1.f / l[1];
    __nv_bfloat16* OgH = g_X3h + (size_t)b * Sc * Dc + h * DKc;
    __nv_bfloat16* OgL = g_X3l + (size_t)b * Sc * Dc + h * DKc;
    const int r0 = q0 + wid * 16 + grp;
#pragma unroll
    for (int jv = 0; jv < 4; ++jv)
#pragma unroll
        for (int t = 0; t < 2; ++t) {
            const int col = jv * 16 + t * 8 + lc2;
            uint32_t h0, l0, h1, l1;
            split2(O[jv][t][0] * inv0, O[jv][t][1] * inv0, h0, l0);
            split2(O[jv][t][2] * inv1, O[jv][t][3] * inv1, h1, l1);
            *(uint32_t*)(OgH + (size_t)r0 * Dc + col)       = h0;
            *(uint32_t*)(OgL + (size_t)r0 * Dc + col)       = l0;
            *(uint32_t*)(OgH + (size_t)(r0 + 8) * Dc + col) = h1;
            *(uint32_t*)(OgL + (size_t)(r0 + 8) * Dc + col) = l1;
        }
}

// ---------------------------------------------------------------------------
// Launch
// ---------------------------------------------------------------------------
extern "C" void kernel_launch(void* const* d_in, const int* in_sizes, int n_in,
                              void* d_out, int out_size)
{
    const float* q  = (const float*)d_in[0];
    const float* k  = (const float*)d_in[1];
    const float* v  = (const float*)d_in[2];
    const float* wq = (const float*)d_in[3];
    const float* bq = (const float*)d_in[4];
    const float* wk = (const float*)d_in[5];
    const float* bk = (const float*)d_in[6];
    const float* wv = (const float*)d_in[7];
    const float* bv = (const float*)d_in[8];
    const float* wo = (const float*)d_in[9];
    const float* bo = (const float*)d_in[10];
    float* out = (float*)d_out;

    __nv_bfloat16 *pXh, *pXl, *pWh, *pWl, *pQh, *pQl, *pKh, *pKl, *pVTh, *pVTl;
    cudaGetSymbolAddress((void**)&pXh, g_X3h);
    cudaGetSymbolAddress((void**)&pXl, g_X3l);
    cudaGetSymbolAddress((void**)&pWh, g_W3h);
    cudaGetSymbolAddress((void**)&pWl, g_W3l);
    cudaGetSymbolAddress((void**)&pQh, g_Qh);
    cudaGetSymbolAddress((void**)&pQl, g_Ql);
    cudaGetSymbolAddress((void**)&pKh, g_Kh);
    cudaGetSymbolAddress((void**)&pKl, g_Kl);
    cudaGetSymbolAddress((void**)&pVTh, g_VTh);
    cudaGetSymbolAddress((void**)&pVTl, g_VTl);

    cudaFuncSetAttribute(gemm_tc_kernel,
                         cudaFuncAttributeMaxDynamicSharedMemorySize, GEMM_SMEM);
    cudaFuncSetAttribute(attn_tc_kernel,
                         cudaFuncAttributeMaxDynamicSharedMemorySize, ATTN_SMEM);

    const int n4 = MD / 4;

    // Batched weight transpose + activation split (q,k,v)
    dim3 cwgrid(Dc / 32, Dc / 32, 3), cwblk(32, 8);
    conv_wT3_kernel<<<cwgrid, cwblk>>>(wq, wk, wv, pWh, pWl);
    dim3 cagrid(n4 / 256, 1, 3);
    conv_act3_kernel<<<cagrid, 256>>>(q, k, v, pXh, pXl, n4);

    // Batched QKV projection (Q split-scaled, K split, V transposed-split)
    dim3 ggrid3(Dc / 128, MROWS / 128, 3);
    gemm_tc_kernel<<<ggrid3, 256, GEMM_SMEM>>>(pXh, pXl, pWh, pWl,
                                               bq, bk, bv,
                                               nullptr,
                                               pQh, pQl, pKh, pKl, pVTh, pVTl, 1);

    // Attention -> split X slot 0
    dim3 agrid(Sc / 128, Bc * Hc);
    attn_tc_kernel<<<agrid, 256, ATTN_SMEM>>>();

    // Output projection
    dim3 cwgrid1(Dc / 32, Dc / 32, 1);
    conv_wT3_kernel<<<cwgrid1, cwblk>>>(wo, wo, wo, pWh, pWl);
    dim3 ggrid1(Dc / 128, MROWS / 128, 1);
    gemm_tc_kernel<<<ggrid1, 256, GEMM_SMEM>>>(pXh, pXl, pWh, pWl,
                                               bo, bo, bo,
                                               out,
                                               pQh, pQl, pKh, pKl, pVTh, pVTl, 0);
}